// round 2
// baseline (speedup 1.0000x reference)
#include <cuda_runtime.h>
#include <cuda_bf16.h>

typedef unsigned long long ull;

#define N_B    4
#define H_N    8
#define D_K    64
#define S_LEN  4096
#define L_LEN  4096
#define NH     (N_B * H_N)       // 32
#define ROWSTR (H_N * D_K)       // 512 floats between consecutive s/l rows
#define SPLIT  16
#define CHUNK  (S_LEN / SPLIT)   // 256
#define STAGE  16                // s-rows per double-buffered stage
#define NSTG   (CHUNK / STAGE)   // 16
#define LT     64                // l-tile for output kernel

// Persistent scratch (device globals; no runtime allocation).
__device__ float g_partKV[SPLIT * NH * D_K * D_K];   // [split][nh][v][d]
__device__ float g_partKs[SPLIT * NH * D_K];         // [split][nh][d]
__device__ float g_KVt[NH * D_K * D_K];              // [nh][v][d]  (transposed KV)
__device__ float g_Ksum[NH * D_K];                   // [nh][d]

__device__ __forceinline__ float elu1(float x) {
    return x > 0.0f ? x + 1.0f : __expf(x);
}

// Packed dual-FMA: d = a*b + d on two fp32 lanes (Blackwell FFMA2 path).
__device__ __forceinline__ void fma2(ull& d, ull a, ull b) {
    asm("fma.rn.f32x2 %0, %1, %2, %0;" : "+l"(d) : "l"(a), "l"(b));
}
__device__ __forceinline__ float2 unpack2(ull p) {
    float2 r;
    asm("mov.b64 {%0, %1}, %2;" : "=f"(r.x), "=f"(r.y) : "l"(p));
    return r;
}

// ---------------------------------------------------------------------------
// Kernel 1: partial KV^T and partial Ksum over an S-chunk.
// 16-row double-buffered stages: LDG next stage -> compute current -> STS next
// -> one __syncthreads per stage. K stored duplicated ([k,k] pairs) so the
// broadcast operand of each packed FMA comes straight from LDS.128.
// Per buffer: K rows at [r*128] (128 floats dup'd), V rows at [2048 + r*64].
// ---------------------------------------------------------------------------
__global__ void __launch_bounds__(256) kv_kernel(const float* __restrict__ Kg,
                                                 const float* __restrict__ Vg) {
    __shared__ float pool[2 * 3072];      // 24 KB; also aliased as transpose stage

    const int split = blockIdx.x;
    const int nh    = blockIdx.y;
    const int n     = nh >> 3;
    const int h     = nh & 7;

    const float* Kb = Kg + ((size_t)n * S_LEN + (size_t)split * CHUNK) * ROWSTR + h * D_K;
    const float* Vb = Vg + ((size_t)n * S_LEN + (size_t)split * CHUNK) * ROWSTR + h * D_K;

    const int t  = threadIdx.x;
    const int tv = t & 15;                // v tile index (4 v's)
    const int td = t >> 4;                // d tile index (4 d's)

    // Loaders: t<128 -> K rows, t>=128 -> V rows. Each covers rows lr and lr+8.
    const bool isK = (t < 128);
    const int  lr  = (t & 127) >> 4;      // 0..7
    const int  lc  = (t & 15) * 4;
    const float* src = (isK ? Kb : Vb) + lc;

    ull acc[4][2];
#pragma unroll
    for (int i = 0; i < 4; i++) { acc[i][0] = 0ull; acc[i][1] = 0ull; }
    float ksum = 0.0f;

    float4 pf0 = *(const float4*)(src + (size_t)lr * ROWSTR);
    float4 pf1 = *(const float4*)(src + (size_t)(lr + 8) * ROWSTR);

    // store a prefetched pair of rows into buffer b
    auto store_stage = [&](int b, float4 a0, float4 a1) {
        float* base = pool + b * 3072;
        if (isK) {
            a0.x = elu1(a0.x); a0.y = elu1(a0.y); a0.z = elu1(a0.z); a0.w = elu1(a0.w);
            a1.x = elu1(a1.x); a1.y = elu1(a1.y); a1.z = elu1(a1.z); a1.w = elu1(a1.w);
            float2* d0 = (float2*)(base + lr * 128 + 2 * lc);
            d0[0] = make_float2(a0.x, a0.x); d0[1] = make_float2(a0.y, a0.y);
            d0[2] = make_float2(a0.z, a0.z); d0[3] = make_float2(a0.w, a0.w);
            float2* d1 = (float2*)(base + (lr + 8) * 128 + 2 * lc);
            d1[0] = make_float2(a1.x, a1.x); d1[1] = make_float2(a1.y, a1.y);
            d1[2] = make_float2(a1.z, a1.z); d1[3] = make_float2(a1.w, a1.w);
        } else {
            *(float4*)(base + 2048 + lr * 64 + lc)       = a0;
            *(float4*)(base + 2048 + (lr + 8) * 64 + lc) = a1;
        }
    };

    store_stage(0, pf0, pf1);
    __syncthreads();

    for (int st = 0; st < NSTG; st++) {
        const int cur = st & 1;
        if (st < NSTG - 1) {
            const float* s2 = src + (size_t)(st + 1) * STAGE * ROWSTR;
            pf0 = *(const float4*)(s2 + (size_t)lr * ROWSTR);
            pf1 = *(const float4*)(s2 + (size_t)(lr + 8) * ROWSTR);
        }
        const float* bK = pool + cur * 3072;
        const float* bV = bK + 2048;

        if (t < 64) {                     // warps 0-1: Ksum over this stage (d = t)
#pragma unroll
            for (int r = 0; r < STAGE; r++) ksum += bK[r * 128 + 2 * t];
        }

#pragma unroll
        for (int r = 0; r < STAGE; r++) {
            ulonglong2 k01 = *(const ulonglong2*)(bK + r * 128 + 8 * td);      // (k0,k0),(k1,k1)
            ulonglong2 k23 = *(const ulonglong2*)(bK + r * 128 + 8 * td + 4);  // (k2,k2),(k3,k3)
            ulonglong2 vv  = *(const ulonglong2*)(bV + r * 64 + 4 * tv);       // (v0,v1),(v2,v3)
            fma2(acc[0][0], k01.x, vv.x); fma2(acc[0][1], k01.x, vv.y);
            fma2(acc[1][0], k01.y, vv.x); fma2(acc[1][1], k01.y, vv.y);
            fma2(acc[2][0], k23.x, vv.x); fma2(acc[2][1], k23.x, vv.y);
            fma2(acc[3][0], k23.y, vv.x); fma2(acc[3][1], k23.y, vv.y);
        }

        if (st < NSTG - 1) store_stage(cur ^ 1, pf0, pf1);
        __syncthreads();
    }

    // Epilogue: transpose via smem (aliases pool; all compute done after sync).
    float* sStage = pool;                 // needs 64*65 = 4160 <= 6144 floats
#pragma unroll
    for (int i = 0; i < 4; i++) {
#pragma unroll
        for (int j = 0; j < 2; j++) {
            float2 p = unpack2(acc[i][j]);
            const int d = 4 * td + i;
            const int v = 4 * tv + 2 * j;
            sStage[v * 65 + d]       = p.x;
            sStage[(v + 1) * 65 + d] = p.y;
        }
    }
    __syncthreads();

    float* dst = g_partKV + ((size_t)split * NH + nh) * (D_K * D_K);
    for (int idx = t; idx < D_K * D_K; idx += 256) {
        const int v = idx >> 6, d = idx & 63;
        dst[idx] = sStage[v * 65 + d];
    }
    if (t < 64) g_partKs[((size_t)split * NH + nh) * D_K + t] = ksum;
}

// ---------------------------------------------------------------------------
// Kernel 2: reduce partials across splits.
// ---------------------------------------------------------------------------
__global__ void __launch_bounds__(256) reduce_kernel() {
    const int nh  = blockIdx.x;
    const int idx = blockIdx.y * 256 + threadIdx.x;
    float s = 0.0f;
#pragma unroll
    for (int p = 0; p < SPLIT; p++)
        s += g_partKV[((size_t)p * NH + nh) * (D_K * D_K) + idx];
    g_KVt[(size_t)nh * (D_K * D_K) + idx] = s;

    if (blockIdx.y == 0 && threadIdx.x < 64) {
        float z = 0.0f;
#pragma unroll
        for (int p = 0; p < SPLIT; p++)
            z += g_partKs[((size_t)p * NH + nh) * D_K + threadIdx.x];
        g_Ksum[nh * D_K + threadIdx.x] = z;
    }
}

// ---------------------------------------------------------------------------
// Kernel 3: out[l][v] = (Qf[l] . KV[:,v]) / (Qf[l] . Ksum + eps)
// 128 threads: 4 warps x 16 v-columns, lanes own rows {lane, lane+32}.
// Pairs run along the reduction dim d: Q rows give free d-pairs (row pad 68
// floats -> conflict-free LDS.128); KV^T rows are warp-uniform broadcasts.
// LDS phases per warp d-iter: 2 Q-loads (8) + 16 bcast (16) per 64 FFMA2.
// ---------------------------------------------------------------------------
__global__ void __launch_bounds__(128, 5) out_kernel(const float* __restrict__ Qg,
                                                     float* __restrict__ Og) {
    __shared__ float sQ[LT][68];          // feature-mapped Q tile, padded
    __shared__ float sKVt[D_K * D_K];     // [v][d]
    __shared__ float sKs[D_K];
    __shared__ float sZ[LT];

    const int nh = blockIdx.y;
    const int l0 = blockIdx.x * LT;
    const int n  = nh >> 3;
    const int h  = nh & 7;

    const float* Qb = Qg + ((size_t)n * L_LEN + l0) * ROWSTR + h * D_K;
    const int t = threadIdx.x;

    // Load + feature-map Q tile (64 rows x 64), coalesced float4 (8 per thread).
    const int lrow = t >> 4;              // 0..7
    const int lcol = (t & 15) * 4;
#pragma unroll
    for (int rr = 0; rr < 8; rr++) {
        const int l = rr * 8 + lrow;
        float4 q = *(const float4*)(Qb + (size_t)l * ROWSTR + lcol);
        q.x = elu1(q.x); q.y = elu1(q.y); q.z = elu1(q.z); q.w = elu1(q.w);
        *(float4*)&sQ[l][lcol] = q;
    }
    // Load KV^T (8 float4 per thread) and Ksum.
    const float4* kvsrc = (const float4*)(g_KVt + (size_t)nh * (D_K * D_K));
#pragma unroll
    for (int rr = 0; rr < 8; rr++)
        ((float4*)sKVt)[rr * 128 + t] = kvsrc[rr * 128 + t];
    if (t < 64) sKs[t] = g_Ksum[nh * D_K + t];
    __syncthreads();

    // Normalizer per row.
    if (t < LT) {
        float acc = 1e-6f;
#pragma unroll
        for (int d = 0; d < D_K; d++) acc += sQ[t][d] * sKs[d];
        sZ[t] = 1.0f / acc;
    }
    __syncthreads();

    const int w    = t >> 5;              // warp id -> v group of 16
    const int lane = t & 31;              // -> l rows lane, lane+32
    const int vb   = w * 16;

    ull acc[2][16];
#pragma unroll
    for (int li = 0; li < 2; li++)
#pragma unroll
        for (int v = 0; v < 16; v++) acc[li][v] = 0ull;

    for (int d = 0; d < D_K; d += 4) {
        const ulonglong2 q0 = *(const ulonglong2*)&sQ[lane][d];
        const ulonglong2 q1 = *(const ulonglong2*)&sQ[lane + 32][d];
#pragma unroll
        for (int v = 0; v < 16; v++) {
            const ulonglong2 kv = *(const ulonglong2*)&sKVt[(vb + v) * D_K + d];
            fma2(acc[0][v], q0.x, kv.x); fma2(acc[0][v], q0.y, kv.y);
            fma2(acc[1][v], q1.x, kv.x); fma2(acc[1][v], q1.y, kv.y);
        }
    }

#pragma unroll
    for (int li = 0; li < 2; li++) {
        const int l = lane + 32 * li;
        const float z = sZ[l];
        float vals[16];
#pragma unroll
        for (int v = 0; v < 16; v++) {
            const float2 p = unpack2(acc[li][v]);
            vals[v] = (p.x + p.y) * z;
        }
        float* orow = Og + ((size_t)(n * L_LEN + l0 + l)) * ROWSTR + h * D_K + vb;
        *(float4*)(orow)      = make_float4(vals[0],  vals[1],  vals[2],  vals[3]);
        *(float4*)(orow + 4)  = make_float4(vals[4],  vals[5],  vals[6],  vals[7]);
        *(float4*)(orow + 8)  = make_float4(vals[8],  vals[9],  vals[10], vals[11]);
        *(float4*)(orow + 12) = make_float4(vals[12], vals[13], vals[14], vals[15]);
    }
}

// ---------------------------------------------------------------------------
extern "C" void kernel_launch(void* const* d_in, const int* in_sizes, int n_in,
                              void* d_out, int out_size) {
    (void)in_sizes; (void)n_in; (void)out_size;
    const float* Q = (const float*)d_in[0];
    const float* K = (const float*)d_in[1];
    const float* V = (const float*)d_in[2];
    float* O = (float*)d_out;

    kv_kernel<<<dim3(SPLIT, NH), 256>>>(K, V);
    reduce_kernel<<<dim3(NH, 16), 256>>>();
    out_kernel<<<dim3(L_LEN / LT, NH), 128>>>(Q, O);
}

// round 5
// speedup vs baseline: 1.6923x; 1.6923x over previous
#include <cuda_runtime.h>

typedef unsigned long long ull;

#define N_B    4
#define H_N    8
#define D_K    64
#define S_LEN  4096
#define L_LEN  4096
#define NH     32
#define ROWSTR 512               // floats between consecutive s/l rows
#define SPLIT  32
#define CHUNK  128               // S_LEN / SPLIT
#define STAGE  8
#define NSTG   16                // CHUNK / STAGE

// Persistent scratch (device globals; no runtime allocation).
__device__ float g_partKV[SPLIT * NH * D_K * D_K];   // [split][nh][d][v]
__device__ float g_partKs[SPLIT * NH * D_K];         // [split][nh][d]
__device__ float g_KV[NH * D_K * D_K];               // [nh][d][v]
__device__ float g_Ksum[NH * D_K];                   // [nh][d]

__device__ __forceinline__ float elu1(float x) {
    return x > 0.0f ? x + 1.0f : __expf(x);
}
__device__ __forceinline__ void fma2(ull& d, ull a, ull b) {
    asm("fma.rn.f32x2 %0, %1, %2, %0;" : "+l"(d) : "l"(a), "l"(b));
}
__device__ __forceinline__ ull dup2(float x) {
    ull r; asm("mov.b64 %0, {%1, %1};" : "=l"(r) : "f"(x)); return r;
}
__device__ __forceinline__ float2 unpack2(ull p) {
    float2 r; asm("mov.b64 {%0, %1}, %2;" : "=f"(r.x), "=f"(r.y) : "l"(p)); return r;
}

// ---------------------------------------------------------------------------
// Kernel 1: partial KV (stored [d][v]) + partial Ksum over an S-chunk.
// 64 threads, thread tile 8d x 8v (interleaved quads), double-buffered stages.
// Per warp-row: 4 LDS.128 : 32 FFMA2 -> FMA-pipe bound (rt=2).
// Ksum accumulated from loader registers (no extra smem reads).
// ---------------------------------------------------------------------------
__global__ void __launch_bounds__(64) kv_kernel(const float* __restrict__ Kg,
                                                const float* __restrict__ Vg) {
    __shared__ __align__(16) float sK[2][STAGE][64];
    __shared__ __align__(16) float sV[2][STAGE][64];
    __shared__ __align__(16) float sRed[STAGE][64];

    const int split = blockIdx.x;
    const int nh    = blockIdx.y;
    const int n     = nh >> 3;
    const int h     = nh & 7;

    const size_t rowbase = ((size_t)n * S_LEN + (size_t)split * CHUNK) * ROWSTR + h * D_K;
    const float* Kb = Kg + rowbase;
    const float* Vb = Vg + rowbase;

    const int t  = threadIdx.x;
    const int td = t >> 3;               // 0..7  (d tile)
    const int tv = t & 7;                // 0..7  (v tile)
    const int rk = t >> 3;               // loader row 0..7
    const int ck = t & 7;                // loader col-quad 0..7

    ull acc[8][4];
#pragma unroll
    for (int i = 0; i < 8; i++)
#pragma unroll
        for (int j = 0; j < 4; j++) acc[i][j] = 0ull;
    float ks[8];
#pragma unroll
    for (int i = 0; i < 8; i++) ks[i] = 0.0f;

    const float* kp = Kb + (size_t)rk * ROWSTR + 4 * ck;
    const float* vp = Vb + (size_t)rk * ROWSTR + 4 * ck;

    float4 pk0 = *(const float4*)kp;
    float4 pk1 = *(const float4*)(kp + 32);
    float4 pv0 = *(const float4*)vp;
    float4 pv1 = *(const float4*)(vp + 32);

    auto store_stage = [&](int b) {
        float4 a = pk0, c = pk1;
        a.x = elu1(a.x); a.y = elu1(a.y); a.z = elu1(a.z); a.w = elu1(a.w);
        c.x = elu1(c.x); c.y = elu1(c.y); c.z = elu1(c.z); c.w = elu1(c.w);
        ks[0] += a.x; ks[1] += a.y; ks[2] += a.z; ks[3] += a.w;
        ks[4] += c.x; ks[5] += c.y; ks[6] += c.z; ks[7] += c.w;
        *(float4*)&sK[b][rk][4 * ck]      = a;
        *(float4*)&sK[b][rk][32 + 4 * ck] = c;
        *(float4*)&sV[b][rk][4 * ck]      = pv0;
        *(float4*)&sV[b][rk][32 + 4 * ck] = pv1;
    };

    store_stage(0);
    __syncthreads();

    for (int st = 0; st < NSTG; st++) {
        const int cur = st & 1;
        if (st < NSTG - 1) {
            const float* kp2 = kp + (size_t)(st + 1) * STAGE * ROWSTR;
            const float* vp2 = vp + (size_t)(st + 1) * STAGE * ROWSTR;
            pk0 = *(const float4*)kp2;
            pk1 = *(const float4*)(kp2 + 32);
            pv0 = *(const float4*)vp2;
            pv1 = *(const float4*)(vp2 + 32);
        }

#pragma unroll
        for (int r = 0; r < STAGE; r++) {
            const float4 ka = *(const float4*)&sK[cur][r][4 * td];
            const float4 kb = *(const float4*)&sK[cur][r][32 + 4 * td];
            const ulonglong2 va = *(const ulonglong2*)&sV[cur][r][4 * tv];
            const ulonglong2 vb = *(const ulonglong2*)&sV[cur][r][32 + 4 * tv];
            const ull k0 = dup2(ka.x), k1 = dup2(ka.y), k2 = dup2(ka.z), k3 = dup2(ka.w);
            const ull k4 = dup2(kb.x), k5 = dup2(kb.y), k6 = dup2(kb.z), k7 = dup2(kb.w);
            fma2(acc[0][0], k0, va.x); fma2(acc[0][1], k0, va.y); fma2(acc[0][2], k0, vb.x); fma2(acc[0][3], k0, vb.y);
            fma2(acc[1][0], k1, va.x); fma2(acc[1][1], k1, va.y); fma2(acc[1][2], k1, vb.x); fma2(acc[1][3], k1, vb.y);
            fma2(acc[2][0], k2, va.x); fma2(acc[2][1], k2, va.y); fma2(acc[2][2], k2, vb.x); fma2(acc[2][3], k2, vb.y);
            fma2(acc[3][0], k3, va.x); fma2(acc[3][1], k3, va.y); fma2(acc[3][2], k3, vb.x); fma2(acc[3][3], k3, vb.y);
            fma2(acc[4][0], k4, va.x); fma2(acc[4][1], k4, va.y); fma2(acc[4][2], k4, vb.x); fma2(acc[4][3], k4, vb.y);
            fma2(acc[5][0], k5, va.x); fma2(acc[5][1], k5, va.y); fma2(acc[5][2], k5, vb.x); fma2(acc[5][3], k5, vb.y);
            fma2(acc[6][0], k6, va.x); fma2(acc[6][1], k6, va.y); fma2(acc[6][2], k6, vb.x); fma2(acc[6][3], k6, vb.y);
            fma2(acc[7][0], k7, va.x); fma2(acc[7][1], k7, va.y); fma2(acc[7][2], k7, vb.x); fma2(acc[7][3], k7, vb.y);
        }

        if (st < NSTG - 1) store_stage(cur ^ 1);
        __syncthreads();
    }

    // Ksum reduce across the 8 row-owner threads per column.
#pragma unroll
    for (int i = 0; i < 4; i++) {
        sRed[rk][4 * ck + i]      = ks[i];
        sRed[rk][32 + 4 * ck + i] = ks[4 + i];
    }
    __syncthreads();
    {
        float s = 0.0f;
#pragma unroll
        for (int r = 0; r < STAGE; r++) s += sRed[r][t];
        g_partKs[((size_t)split * NH + nh) * D_K + t] = s;
    }

    // Store partial KV as [d][v] (what the out pass wants).
    float* dst = g_partKV + ((size_t)split * NH + nh) * (D_K * D_K);
#pragma unroll
    for (int di = 0; di < 8; di++) {
        const int d = (di < 4) ? (4 * td + di) : (32 + 4 * td + (di - 4));
        const float2 p0 = unpack2(acc[di][0]);
        const float2 p1 = unpack2(acc[di][1]);
        *(float4*)(dst + d * 64 + 4 * tv) = make_float4(p0.x, p0.y, p1.x, p1.y);
        const float2 p2 = unpack2(acc[di][2]);
        const float2 p3 = unpack2(acc[di][3]);
        *(float4*)(dst + d * 64 + 32 + 4 * tv) = make_float4(p2.x, p2.y, p3.x, p3.y);
    }
}

// ---------------------------------------------------------------------------
// Kernel 2: reduce partials across splits.
// ---------------------------------------------------------------------------
__global__ void __launch_bounds__(256) reduce_kernel() {
    const int nh = blockIdx.x;
    const int i4 = blockIdx.y * 256 + threadIdx.x;   // float4 index 0..1023
    float4 s = make_float4(0.f, 0.f, 0.f, 0.f);
    const float4* base = (const float4*)g_partKV;
#pragma unroll
    for (int p = 0; p < SPLIT; p++) {
        const float4 v = base[((size_t)p * NH + nh) * 1024 + i4];
        s.x += v.x; s.y += v.y; s.z += v.z; s.w += v.w;
    }
    ((float4*)g_KV)[(size_t)nh * 1024 + i4] = s;

    if (blockIdx.y == 0 && threadIdx.x < 64) {
        float z = 0.0f;
#pragma unroll
        for (int p = 0; p < SPLIT; p++)
            z += g_partKs[((size_t)p * NH + nh) * D_K + threadIdx.x];
        g_Ksum[nh * D_K + threadIdx.x] = z;
    }
}

// ---------------------------------------------------------------------------
// Kernel 3: out[l][v] = (Qf[l] . KV[:,v]) * Z[l].
// 128 threads, block tile 128 l x 64 v, thread tile 8l x 8v.
// Thread rows are {tl + 16*j}: within a warp tl is 4 CONSECUTIVE values so
// the broadcast LDS.32 of sQ hits banks (4*tl + d) mod 32 -> conflict-free.
// sQ row stride 68 floats = 272B (16B multiple -> float4-aligned stores).
// Per warp-d: 8 LDS.32 + 2 LDS.128 : 32 FFMA2.
// ---------------------------------------------------------------------------
__global__ void __launch_bounds__(128) out_kernel(const float* __restrict__ Qg,
                                                  float* __restrict__ Og) {
    __shared__ __align__(16) float sQ[128][68];
    __shared__ __align__(16) float sKV[32][64];
    __shared__ __align__(16) float sKs[64];
    __shared__ __align__(16) float sZ[128];

    const int nh = blockIdx.y;
    const int l0 = blockIdx.x * 128;
    const int n  = nh >> 3;
    const int h  = nh & 7;

    const float* Qb = Qg + ((size_t)n * L_LEN + l0) * ROWSTR + h * D_K;
    const int t = threadIdx.x;

    // Load + feature-map Q tile (128 x 64).
    const int qr = t >> 4;               // 0..7
    const int qc = (t & 15) * 4;
#pragma unroll
    for (int p = 0; p < 16; p++) {
        const int l = p * 8 + qr;
        float4 q = *(const float4*)(Qb + (size_t)l * ROWSTR + qc);
        q.x = elu1(q.x); q.y = elu1(q.y); q.z = elu1(q.z); q.w = elu1(q.w);
        *(float4*)&sQ[l][qc] = q;
    }
    if (t < 64) sKs[t] = g_Ksum[nh * D_K + t];
    __syncthreads();

    // Normalizer: thread t handles row l = t.
    {
        float a = 1e-6f;
#pragma unroll
        for (int d = 0; d < D_K; d++) a += sQ[t][d] * sKs[d];
        sZ[t] = 1.0f / a;
    }
    __syncthreads();

    const int tl = t >> 3;               // 0..15; owns rows tl + 16*j
    const int tv = t & 7;                // v quads {4tv..}, {32+4tv..}

    ull acc[8][4];
#pragma unroll
    for (int j = 0; j < 8; j++)
#pragma unroll
        for (int q = 0; q < 4; q++) acc[j][q] = 0ull;

    const float* kvsrc = g_KV + (size_t)nh * (D_K * D_K);

    for (int half = 0; half < 2; half++) {
        // Load d-half of KV (32 x 64 floats = 512 float4).
#pragma unroll
        for (int i = 0; i < 4; i++)
            ((float4*)sKV)[i * 128 + t] = ((const float4*)(kvsrc + half * 2048))[i * 128 + t];
        __syncthreads();

#pragma unroll 2
        for (int dd = 0; dd < 32; dd++) {
            const ulonglong2 ba = *(const ulonglong2*)&sKV[dd][4 * tv];
            const ulonglong2 bb = *(const ulonglong2*)&sKV[dd][32 + 4 * tv];
            const int d = half * 32 + dd;
#pragma unroll
            for (int j = 0; j < 8; j++) {
                const ull q = dup2(sQ[tl + 16 * j][d]);
                fma2(acc[j][0], q, ba.x); fma2(acc[j][1], q, ba.y);
                fma2(acc[j][2], q, bb.x); fma2(acc[j][3], q, bb.y);
            }
        }
        __syncthreads();
    }

    // Epilogue: scale by Z and store (rows tl + 16*j, coalesced float4).
#pragma unroll
    for (int j = 0; j < 8; j++) {
        const int l = tl + 16 * j;
        const float z = sZ[l];
        float* orow = Og + ((size_t)(n * L_LEN + l0 + l)) * ROWSTR + h * D_K;
        const float2 p0 = unpack2(acc[j][0]);
        const float2 p1 = unpack2(acc[j][1]);
        *(float4*)(orow + 4 * tv) = make_float4(p0.x * z, p0.y * z, p1.x * z, p1.y * z);
        const float2 p2 = unpack2(acc[j][2]);
        const float2 p3 = unpack2(acc[j][3]);
        *(float4*)(orow + 32 + 4 * tv) = make_float4(p2.x * z, p2.y * z, p3.x * z, p3.y * z);
    }
}

// ---------------------------------------------------------------------------
extern "C" void kernel_launch(void* const* d_in, const int* in_sizes, int n_in,
                              void* d_out, int out_size) {
    (void)in_sizes; (void)n_in; (void)out_size;
    const float* Q = (const float*)d_in[0];
    const float* K = (const float*)d_in[1];
    const float* V = (const float*)d_in[2];
    float* O = (float*)d_out;

    kv_kernel<<<dim3(SPLIT, NH), 64>>>(K, V);
    reduce_kernel<<<dim3(NH, 4), 256>>>();
    out_kernel<<<dim3(L_LEN / 128, NH), 128>>>(Q, O);
}

// round 6
// speedup vs baseline: 1.7352x; 1.0254x over previous
#include <cuda_runtime.h>

typedef unsigned long long ull;

#define N_B    4
#define H_N    8
#define D_K    64
#define S_LEN  4096
#define L_LEN  4096
#define NH     32
#define ROWSTR 512               // floats between consecutive s/l rows
#define SPLIT  32
#define CHUNK  128               // S_LEN / SPLIT
#define STAGE  8
#define NSTG   16                // CHUNK / STAGE
#define KDSTR  132               // padded dup'd-K row stride (floats, 16B multiple)

// Persistent scratch (device globals; no runtime allocation).
__device__ float g_partKV[SPLIT * NH * D_K * D_K];   // [split][nh][d][v]
__device__ float g_partKs[SPLIT * NH * D_K];         // [split][nh][d]
__device__ float g_KV[NH * D_K * D_K];               // [nh][d][v]
__device__ float g_Ksum[NH * D_K];                   // [nh][d]

__device__ __forceinline__ float elu1(float x) {
    return x > 0.0f ? x + 1.0f : __expf(x);
}
__device__ __forceinline__ void fma2(ull& d, ull a, ull b) {
    asm("fma.rn.f32x2 %0, %1, %2, %0;" : "+l"(d) : "l"(a), "l"(b));
}
__device__ __forceinline__ ull dup2(float x) {
    ull r; asm("mov.b64 %0, {%1, %1};" : "=l"(r) : "f"(x)); return r;
}
__device__ __forceinline__ float2 unpack2(ull p) {
    float2 r; asm("mov.b64 {%0, %1}, %2;" : "=f"(r.x), "=f"(r.y) : "l"(p)); return r;
}

// ---------------------------------------------------------------------------
// Kernel 1: partial KV (stored [d][v]) + partial Ksum over an S-chunk.
// 64 threads, thread tile 8d (contiguous) x 8v (interleaved quads).
// K is stored PRE-DUPLICATED ((k,k) float2 pairs) by the loader, so the hot
// loop is pure LDS.128 + FFMA2: 4 K-loads (broadcast, ~1-2 phases) +
// 2 V-loads + 32 FFMA2 per warp-row. No MOVs, no cross-pipe chains.
// Ksum accumulated from loader registers.
// ---------------------------------------------------------------------------
__global__ void __launch_bounds__(64) kv_kernel(const float* __restrict__ Kg,
                                                const float* __restrict__ Vg) {
    __shared__ __align__(16) float sKd[2][STAGE][KDSTR];  // dup'd K: [r][2d..2d+1]
    __shared__ __align__(16) float sV[2][STAGE][64];
    __shared__ __align__(16) float sRed[STAGE][64];

    const int split = blockIdx.x;
    const int nh    = blockIdx.y;
    const int n     = nh >> 3;
    const int h     = nh & 7;

    const size_t rowbase = ((size_t)n * S_LEN + (size_t)split * CHUNK) * ROWSTR + h * D_K;
    const float* Kb = Kg + rowbase;
    const float* Vb = Vg + rowbase;

    const int t  = threadIdx.x;
    const int td = t >> 3;               // 0..7  -> d = 8*td .. 8*td+7
    const int tv = t & 7;                // 0..7  -> v quads {4tv..}, {32+4tv..}
    const int rk = t >> 3;               // loader row 0..7
    const int ck = t & 7;                // loader col-quad 0..7

    ull acc[8][4];
#pragma unroll
    for (int i = 0; i < 8; i++)
#pragma unroll
        for (int j = 0; j < 4; j++) acc[i][j] = 0ull;
    float ks[8];
#pragma unroll
    for (int i = 0; i < 8; i++) ks[i] = 0.0f;

    const float* kp = Kb + (size_t)rk * ROWSTR + 4 * ck;
    const float* vp = Vb + (size_t)rk * ROWSTR + 4 * ck;

    float4 pk0 = *(const float4*)kp;
    float4 pk1 = *(const float4*)(kp + 32);
    float4 pv0 = *(const float4*)vp;
    float4 pv1 = *(const float4*)(vp + 32);

    auto store_stage = [&](int b) {
        float4 a = pk0, c = pk1;
        a.x = elu1(a.x); a.y = elu1(a.y); a.z = elu1(a.z); a.w = elu1(a.w);
        c.x = elu1(c.x); c.y = elu1(c.y); c.z = elu1(c.z); c.w = elu1(c.w);
        ks[0] += a.x; ks[1] += a.y; ks[2] += a.z; ks[3] += a.w;
        ks[4] += c.x; ks[5] += c.y; ks[6] += c.z; ks[7] += c.w;
        // duplicated pairs: d = 4ck+i at floats [8ck + 2i], d = 32+4ck+i at [64 + 8ck + 2i]
        float2* d0 = (float2*)&sKd[b][rk][8 * ck];
        d0[0] = make_float2(a.x, a.x); d0[1] = make_float2(a.y, a.y);
        d0[2] = make_float2(a.z, a.z); d0[3] = make_float2(a.w, a.w);
        float2* d1 = (float2*)&sKd[b][rk][64 + 8 * ck];
        d1[0] = make_float2(c.x, c.x); d1[1] = make_float2(c.y, c.y);
        d1[2] = make_float2(c.z, c.z); d1[3] = make_float2(c.w, c.w);
        *(float4*)&sV[b][rk][4 * ck]      = pv0;
        *(float4*)&sV[b][rk][32 + 4 * ck] = pv1;
    };

    store_stage(0);
    __syncthreads();

    for (int st = 0; st < NSTG; st++) {
        const int cur = st & 1;
        if (st < NSTG - 1) {
            const float* kp2 = kp + (size_t)(st + 1) * STAGE * ROWSTR;
            const float* vp2 = vp + (size_t)(st + 1) * STAGE * ROWSTR;
            pk0 = *(const float4*)kp2;
            pk1 = *(const float4*)(kp2 + 32);
            pv0 = *(const float4*)vp2;
            pv1 = *(const float4*)(vp2 + 32);
        }

#pragma unroll
        for (int r = 0; r < STAGE; r++) {
            // 4 LDS.128 of dup'd K pairs: d = 8td+0..7
            const ulonglong2 kA = *(const ulonglong2*)&sKd[cur][r][16 * td];
            const ulonglong2 kB = *(const ulonglong2*)&sKd[cur][r][16 * td + 4];
            const ulonglong2 kC = *(const ulonglong2*)&sKd[cur][r][16 * td + 8];
            const ulonglong2 kD = *(const ulonglong2*)&sKd[cur][r][16 * td + 12];
            const ulonglong2 va = *(const ulonglong2*)&sV[cur][r][4 * tv];
            const ulonglong2 vb = *(const ulonglong2*)&sV[cur][r][32 + 4 * tv];
            fma2(acc[0][0], kA.x, va.x); fma2(acc[0][1], kA.x, va.y); fma2(acc[0][2], kA.x, vb.x); fma2(acc[0][3], kA.x, vb.y);
            fma2(acc[1][0], kA.y, va.x); fma2(acc[1][1], kA.y, va.y); fma2(acc[1][2], kA.y, vb.x); fma2(acc[1][3], kA.y, vb.y);
            fma2(acc[2][0], kB.x, va.x); fma2(acc[2][1], kB.x, va.y); fma2(acc[2][2], kB.x, vb.x); fma2(acc[2][3], kB.x, vb.y);
            fma2(acc[3][0], kB.y, va.x); fma2(acc[3][1], kB.y, va.y); fma2(acc[3][2], kB.y, vb.x); fma2(acc[3][3], kB.y, vb.y);
            fma2(acc[4][0], kC.x, va.x); fma2(acc[4][1], kC.x, va.y); fma2(acc[4][2], kC.x, vb.x); fma2(acc[4][3], kC.x, vb.y);
            fma2(acc[5][0], kC.y, va.x); fma2(acc[5][1], kC.y, va.y); fma2(acc[5][2], kC.y, vb.x); fma2(acc[5][3], kC.y, vb.y);
            fma2(acc[6][0], kD.x, va.x); fma2(acc[6][1], kD.x, va.y); fma2(acc[6][2], kD.x, vb.x); fma2(acc[6][3], kD.x, vb.y);
            fma2(acc[7][0], kD.y, va.x); fma2(acc[7][1], kD.y, va.y); fma2(acc[7][2], kD.y, vb.x); fma2(acc[7][3], kD.y, vb.y);
        }

        if (st < NSTG - 1) store_stage(cur ^ 1);
        __syncthreads();
    }

    // Ksum reduce across the 8 row-owner threads per column.
#pragma unroll
    for (int i = 0; i < 4; i++) {
        sRed[rk][4 * ck + i]      = ks[i];
        sRed[rk][32 + 4 * ck + i] = ks[4 + i];
    }
    __syncthreads();
    {
        float s = 0.0f;
#pragma unroll
        for (int r = 0; r < STAGE; r++) s += sRed[r][t];
        g_partKs[((size_t)split * NH + nh) * D_K + t] = s;
    }

    // Store partial KV as [d][v] (d = 8*td + di).
    float* dst = g_partKV + ((size_t)split * NH + nh) * (D_K * D_K);
#pragma unroll
    for (int di = 0; di < 8; di++) {
        const int d = 8 * td + di;
        const float2 p0 = unpack2(acc[di][0]);
        const float2 p1 = unpack2(acc[di][1]);
        *(float4*)(dst + d * 64 + 4 * tv) = make_float4(p0.x, p0.y, p1.x, p1.y);
        const float2 p2 = unpack2(acc[di][2]);
        const float2 p3 = unpack2(acc[di][3]);
        *(float4*)(dst + d * 64 + 32 + 4 * tv) = make_float4(p2.x, p2.y, p3.x, p3.y);
    }
}

// ---------------------------------------------------------------------------
// Kernel 2: reduce partials across splits.
// ---------------------------------------------------------------------------
__global__ void __launch_bounds__(256) reduce_kernel() {
    const int nh = blockIdx.x;
    const int i4 = blockIdx.y * 256 + threadIdx.x;   // float4 index 0..1023
    float4 s = make_float4(0.f, 0.f, 0.f, 0.f);
    const float4* base = (const float4*)g_partKV;
#pragma unroll
    for (int p = 0; p < SPLIT; p++) {
        const float4 v = base[((size_t)p * NH + nh) * 1024 + i4];
        s.x += v.x; s.y += v.y; s.z += v.z; s.w += v.w;
    }
    ((float4*)g_KV)[(size_t)nh * 1024 + i4] = s;

    if (blockIdx.y == 0 && threadIdx.x < 64) {
        float z = 0.0f;
#pragma unroll
        for (int p = 0; p < SPLIT; p++)
            z += g_partKs[((size_t)p * NH + nh) * D_K + threadIdx.x];
        g_Ksum[nh * D_K + threadIdx.x] = z;
    }
}

// ---------------------------------------------------------------------------
// Kernel 3: out[l][v] = (Qf[l] . KV[:,v]) * Z[l].
// 128 threads, block tile 128 l x 64 v, thread tile 4l x 16v:
//   rows l = tl + 32j (tl = t>>2, j=0..3)  -> sQ banks 4*tl+d, conflict-free
//   v quads 4*tv + 16m (tv = t&3, m=0..3)  -> 4-distinct-address LDS.128
// Per dd: 4 LDS.32 + 4 MOV + 4 LDS.128 + 32 FFMA2 (40 issue slots / 64 cyc).
// ---------------------------------------------------------------------------
__global__ void __launch_bounds__(128) out_kernel(const float* __restrict__ Qg,
                                                  float* __restrict__ Og) {
    __shared__ __align__(16) float sQ[128][68];
    __shared__ __align__(16) float sKV[32][64];
    __shared__ __align__(16) float sKs[64];
    __shared__ __align__(16) float sZ[128];

    const int nh = blockIdx.y;
    const int l0 = blockIdx.x * 128;
    const int n  = nh >> 3;
    const int h  = nh & 7;

    const float* Qb = Qg + ((size_t)n * L_LEN + l0) * ROWSTR + h * D_K;
    const int t = threadIdx.x;

    // Load + feature-map Q tile (128 x 64).
    const int qr = t >> 4;               // 0..7
    const int qc = (t & 15) * 4;
#pragma unroll
    for (int p = 0; p < 16; p++) {
        const int l = p * 8 + qr;
        float4 q = *(const float4*)(Qb + (size_t)l * ROWSTR + qc);
        q.x = elu1(q.x); q.y = elu1(q.y); q.z = elu1(q.z); q.w = elu1(q.w);
        *(float4*)&sQ[l][qc] = q;
    }
    if (t < 64) sKs[t] = g_Ksum[nh * D_K + t];
    __syncthreads();

    // Normalizer: thread t handles row l = t.
    {
        float a = 1e-6f;
#pragma unroll
        for (int d = 0; d < D_K; d++) a += sQ[t][d] * sKs[d];
        sZ[t] = 1.0f / a;
    }
    __syncthreads();

    const int tl = t >> 2;               // 0..31; rows tl + 32*j
    const int tv = t & 3;                // v quads 4*tv + 16*m

    ull acc[4][4][2];
#pragma unroll
    for (int j = 0; j < 4; j++)
#pragma unroll
        for (int m = 0; m < 4; m++) { acc[j][m][0] = 0ull; acc[j][m][1] = 0ull; }

    const float* kvsrc = g_KV + (size_t)nh * (D_K * D_K);

    for (int half = 0; half < 2; half++) {
        // Load d-half of KV (32 x 64 floats = 512 float4).
#pragma unroll
        for (int i = 0; i < 4; i++)
            ((float4*)sKV)[i * 128 + t] = ((const float4*)(kvsrc + half * 2048))[i * 128 + t];
        __syncthreads();

#pragma unroll 4
        for (int dd = 0; dd < 32; dd++) {
            const int d = half * 32 + dd;
            ulonglong2 kv[4];
#pragma unroll
            for (int m = 0; m < 4; m++)
                kv[m] = *(const ulonglong2*)&sKV[dd][4 * tv + 16 * m];
            ull q[4];
#pragma unroll
            for (int j = 0; j < 4; j++) q[j] = dup2(sQ[tl + 32 * j][d]);
#pragma unroll
            for (int j = 0; j < 4; j++) {
#pragma unroll
                for (int m = 0; m < 4; m++) {
                    fma2(acc[j][m][0], q[j], kv[m].x);
                    fma2(acc[j][m][1], q[j], kv[m].y);
                }
            }
        }
        __syncthreads();
    }

    // Epilogue: scale by Z and store (rows tl + 32*j, float4 per v-quad).
#pragma unroll
    for (int j = 0; j < 4; j++) {
        const int l = tl + 32 * j;
        const float z = sZ[l];
        float* orow = Og + ((size_t)(n * L_LEN + l0 + l)) * ROWSTR + h * D_K;
#pragma unroll
        for (int m = 0; m < 4; m++) {
            const float2 p0 = unpack2(acc[j][m][0]);
            const float2 p1 = unpack2(acc[j][m][1]);
            *(float4*)(orow + 4 * tv + 16 * m) =
                make_float4(p0.x * z, p0.y * z, p1.x * z, p1.y * z);
        }
    }
}

// ---------------------------------------------------------------------------
extern "C" void kernel_launch(void* const* d_in, const int* in_sizes, int n_in,
                              void* d_out, int out_size) {
    (void)in_sizes; (void)n_in; (void)out_size;
    const float* Q = (const float*)d_in[0];
    const float* K = (const float*)d_in[1];
    const float* V = (const float*)d_in[2];
    float* O = (float*)d_out;

    kv_kernel<<<dim3(SPLIT, NH), 64>>>(K, V);
    reduce_kernel<<<dim3(NH, 4), 256>>>();
    out_kernel<<<dim3(L_LEN / 128, NH), 128>>>(Q, O);
}

// round 7
// speedup vs baseline: 1.9848x; 1.1438x over previous
#include <cuda_runtime.h>

typedef unsigned long long ull;

#define N_B    4
#define H_N    8
#define D_K    64
#define S_LEN  4096
#define L_LEN  4096
#define NH     32
#define ROWSTR 512               // floats between consecutive s/l rows
#define SPLIT  32
#define CHUNK  128               // S_LEN / SPLIT
#define STAGE  16
#define NSTG   (CHUNK / STAGE)   // 8

// Persistent scratch (device globals; no runtime allocation).
__device__ float g_partKV[SPLIT * NH * D_K * D_K];   // [split][nh][d][v]
__device__ float g_partKs[SPLIT * NH * D_K];         // [split][nh][d]
__device__ float g_KV[NH * D_K * D_K];               // [nh][d][v]
__device__ float g_Ksum[NH * D_K];                   // [nh][d]

__device__ __forceinline__ float elu1(float x) {
    return x > 0.0f ? x + 1.0f : __expf(x);
}
__device__ __forceinline__ void fma2(ull& d, ull a, ull b) {
    asm("fma.rn.f32x2 %0, %1, %2, %0;" : "+l"(d) : "l"(a), "l"(b));
}
__device__ __forceinline__ ull dup2(float x) {
    ull r; asm("mov.b64 %0, {%1, %1};" : "=l"(r) : "f"(x)); return r;
}
__device__ __forceinline__ float2 unpack2(ull p) {
    float2 r; asm("mov.b64 {%0, %1}, %2;" : "=f"(r.x), "=f"(r.y) : "l"(p)); return r;
}

// ---------------------------------------------------------------------------
// Kernel 1: partial KV (stored [d][v]) + partial Ksum over an S-chunk.
// 128 threads, thread tile 4d x 8v (16 acc ull = 32 regs -> high occupancy).
// 16-row double-buffered stages. Per warp-row: 1 K-LDS.128 (4-quad bcast) +
// 2 V-LDS.128 + 4 dup MOVs + 16 FFMA2. Ksum from loader registers.
// ---------------------------------------------------------------------------
__global__ void __launch_bounds__(128) kv_kernel(const float* __restrict__ Kg,
                                                 const float* __restrict__ Vg) {
    __shared__ __align__(16) float sK[2][STAGE][64];
    __shared__ __align__(16) float sV[2][STAGE][64];
    __shared__ __align__(16) float sRed[8][64];

    const int split = blockIdx.x;
    const int nh    = blockIdx.y;
    const int n     = nh >> 3;
    const int h     = nh & 7;

    const size_t rowbase = ((size_t)n * S_LEN + (size_t)split * CHUNK) * ROWSTR + h * D_K;
    const float* Kb = Kg + rowbase;
    const float* Vb = Vg + rowbase;

    const int t  = threadIdx.x;
    const int td = t >> 3;               // 0..15 -> d = 4*td .. 4*td+3
    const int tv = t & 7;                // 0..7  -> v quads {4tv}, {32+4tv}
    const int lrow = t >> 4;             // loader row 0..7 (also +8)
    const int ck   = t & 15;             // loader col-quad 0..15

    ull acc[4][4];
#pragma unroll
    for (int i = 0; i < 4; i++)
#pragma unroll
        for (int j = 0; j < 4; j++) acc[i][j] = 0ull;
    float ks[4];
#pragma unroll
    for (int i = 0; i < 4; i++) ks[i] = 0.0f;

    const float* kp = Kb + (size_t)lrow * ROWSTR + 4 * ck;
    const float* vp = Vb + (size_t)lrow * ROWSTR + 4 * ck;

    float4 pk0 = *(const float4*)kp;
    float4 pk1 = *(const float4*)(kp + 8 * ROWSTR);
    float4 pv0 = *(const float4*)vp;
    float4 pv1 = *(const float4*)(vp + 8 * ROWSTR);

    auto store_stage = [&](int b) {
        float4 a = pk0, c = pk1;
        a.x = elu1(a.x); a.y = elu1(a.y); a.z = elu1(a.z); a.w = elu1(a.w);
        c.x = elu1(c.x); c.y = elu1(c.y); c.z = elu1(c.z); c.w = elu1(c.w);
        ks[0] += a.x + c.x; ks[1] += a.y + c.y;
        ks[2] += a.z + c.z; ks[3] += a.w + c.w;
        *(float4*)&sK[b][lrow][4 * ck]     = a;
        *(float4*)&sK[b][lrow + 8][4 * ck] = c;
        *(float4*)&sV[b][lrow][4 * ck]     = pv0;
        *(float4*)&sV[b][lrow + 8][4 * ck] = pv1;
    };

    store_stage(0);
    __syncthreads();

    for (int st = 0; st < NSTG; st++) {
        const int cur = st & 1;
        if (st < NSTG - 1) {
            const float* kp2 = kp + (size_t)(st + 1) * STAGE * ROWSTR;
            const float* vp2 = vp + (size_t)(st + 1) * STAGE * ROWSTR;
            pk0 = *(const float4*)kp2;
            pk1 = *(const float4*)(kp2 + 8 * ROWSTR);
            pv0 = *(const float4*)vp2;
            pv1 = *(const float4*)(vp2 + 8 * ROWSTR);
        }

#pragma unroll
        for (int r = 0; r < STAGE; r++) {
            const float4 ka = *(const float4*)&sK[cur][r][4 * td];
            const ulonglong2 va = *(const ulonglong2*)&sV[cur][r][4 * tv];
            const ulonglong2 vb = *(const ulonglong2*)&sV[cur][r][32 + 4 * tv];
            const ull k0 = dup2(ka.x), k1 = dup2(ka.y), k2 = dup2(ka.z), k3 = dup2(ka.w);
            fma2(acc[0][0], k0, va.x); fma2(acc[0][1], k0, va.y); fma2(acc[0][2], k0, vb.x); fma2(acc[0][3], k0, vb.y);
            fma2(acc[1][0], k1, va.x); fma2(acc[1][1], k1, va.y); fma2(acc[1][2], k1, vb.x); fma2(acc[1][3], k1, vb.y);
            fma2(acc[2][0], k2, va.x); fma2(acc[2][1], k2, va.y); fma2(acc[2][2], k2, vb.x); fma2(acc[2][3], k2, vb.y);
            fma2(acc[3][0], k3, va.x); fma2(acc[3][1], k3, va.y); fma2(acc[3][2], k3, vb.x); fma2(acc[3][3], k3, vb.y);
        }

        if (st < NSTG - 1) store_stage(cur ^ 1);
        __syncthreads();
    }

    // Ksum reduce across the 8 loader-row groups.
#pragma unroll
    for (int i = 0; i < 4; i++) sRed[lrow][4 * ck + i] = ks[i];
    __syncthreads();
    if (t < 64) {
        float s = 0.0f;
#pragma unroll
        for (int r = 0; r < 8; r++) s += sRed[r][t];
        g_partKs[((size_t)split * NH + nh) * D_K + t] = s;
    }

    // Store partial KV as [d][v] (d = 4*td + di).
    float* dst = g_partKV + ((size_t)split * NH + nh) * (D_K * D_K);
#pragma unroll
    for (int di = 0; di < 4; di++) {
        const int d = 4 * td + di;
        const float2 p0 = unpack2(acc[di][0]);
        const float2 p1 = unpack2(acc[di][1]);
        *(float4*)(dst + d * 64 + 4 * tv) = make_float4(p0.x, p0.y, p1.x, p1.y);
        const float2 p2 = unpack2(acc[di][2]);
        const float2 p3 = unpack2(acc[di][3]);
        *(float4*)(dst + d * 64 + 32 + 4 * tv) = make_float4(p2.x, p2.y, p3.x, p3.y);
    }
}

// ---------------------------------------------------------------------------
// Kernel 2: reduce partials across splits.
// ---------------------------------------------------------------------------
__global__ void __launch_bounds__(256) reduce_kernel() {
    const int nh = blockIdx.x;
    const int i4 = blockIdx.y * 256 + threadIdx.x;   // float4 index 0..1023
    float4 s = make_float4(0.f, 0.f, 0.f, 0.f);
    const float4* base = (const float4*)g_partKV;
#pragma unroll
    for (int p = 0; p < SPLIT; p++) {
        const float4 v = base[((size_t)p * NH + nh) * 1024 + i4];
        s.x += v.x; s.y += v.y; s.z += v.z; s.w += v.w;
    }
    ((float4*)g_KV)[(size_t)nh * 1024 + i4] = s;

    if (blockIdx.y == 0 && threadIdx.x < 64) {
        float z = 0.0f;
#pragma unroll
        for (int p = 0; p < SPLIT; p++)
            z += g_partKs[((size_t)p * NH + nh) * D_K + threadIdx.x];
        g_Ksum[nh * D_K + threadIdx.x] = z;
    }
}

// ---------------------------------------------------------------------------
// Kernel 3: out[l][v] = (Qf[l] . KV[:,v]) * Z[l].
// 128 threads, block tile 64 l x 64 v, thread tile 4l x 8v (32 acc regs).
// Rows l = tl + 16*j (tl = t>>3 consecutive within warp -> sQ broadcast
// banks (4*tl + d) mod 32, conflict-free). sQ row stride 68 (16B-aligned).
// Per dd: 4 LDS.32 + 4 MOV + 2 LDS.128 + 16 FFMA2.
// ---------------------------------------------------------------------------
__global__ void __launch_bounds__(128) out_kernel(const float* __restrict__ Qg,
                                                  float* __restrict__ Og) {
    __shared__ __align__(16) float sQ[64][68];
    __shared__ __align__(16) float sKV[32][64];
    __shared__ __align__(16) float sKs[64];
    __shared__ __align__(16) float sZ[64];

    const int nh = blockIdx.y;
    const int l0 = blockIdx.x * 64;
    const int n  = nh >> 3;
    const int h  = nh & 7;

    const float* Qb = Qg + ((size_t)n * L_LEN + l0) * ROWSTR + h * D_K;
    const int t = threadIdx.x;

    // Load + feature-map Q tile (64 x 64): 8 float4 per thread.
    const int qr = t >> 4;               // 0..7
    const int qc = (t & 15) * 4;
#pragma unroll
    for (int p = 0; p < 8; p++) {
        const int l = p * 8 + qr;
        float4 q = *(const float4*)(Qb + (size_t)l * ROWSTR + qc);
        q.x = elu1(q.x); q.y = elu1(q.y); q.z = elu1(q.z); q.w = elu1(q.w);
        *(float4*)&sQ[l][qc] = q;
    }
    if (t < 64) sKs[t] = g_Ksum[nh * D_K + t];
    __syncthreads();

    // Normalizer: threads 0..63 handle row l = t.
    if (t < 64) {
        float a = 1e-6f;
#pragma unroll
        for (int d = 0; d < D_K; d++) a += sQ[t][d] * sKs[d];
        sZ[t] = 1.0f / a;
    }
    __syncthreads();

    const int tl = t >> 3;               // 0..15; rows tl + 16*j
    const int tv = t & 7;                // v quads {4tv}, {32+4tv}

    ull acc[4][4];
#pragma unroll
    for (int j = 0; j < 4; j++)
#pragma unroll
        for (int q = 0; q < 4; q++) acc[j][q] = 0ull;

    const float* kvsrc = g_KV + (size_t)nh * (D_K * D_K);

    for (int half = 0; half < 2; half++) {
        // Load d-half of KV (32 x 64 floats = 512 float4): 4 per thread.
#pragma unroll
        for (int i = 0; i < 4; i++)
            ((float4*)sKV)[i * 128 + t] = ((const float4*)(kvsrc + half * 2048))[i * 128 + t];
        __syncthreads();

#pragma unroll 4
        for (int dd = 0; dd < 32; dd++) {
            const int d = half * 32 + dd;
            const ulonglong2 ba = *(const ulonglong2*)&sKV[dd][4 * tv];
            const ulonglong2 bb = *(const ulonglong2*)&sKV[dd][32 + 4 * tv];
            ull q[4];
#pragma unroll
            for (int j = 0; j < 4; j++) q[j] = dup2(sQ[tl + 16 * j][d]);
#pragma unroll
            for (int j = 0; j < 4; j++) {
                fma2(acc[j][0], q[j], ba.x); fma2(acc[j][1], q[j], ba.y);
                fma2(acc[j][2], q[j], bb.x); fma2(acc[j][3], q[j], bb.y);
            }
        }
        __syncthreads();
    }

    // Epilogue: scale by Z and store (rows tl + 16*j).
#pragma unroll
    for (int j = 0; j < 4; j++) {
        const int l = tl + 16 * j;
        const float z = sZ[l];
        float* orow = Og + ((size_t)(n * L_LEN + l0 + l)) * ROWSTR + h * D_K;
        const float2 p0 = unpack2(acc[j][0]);
        const float2 p1 = unpack2(acc[j][1]);
        *(float4*)(orow + 4 * tv) = make_float4(p0.x * z, p0.y * z, p1.x * z, p1.y * z);
        const float2 p2 = unpack2(acc[j][2]);
        const float2 p3 = unpack2(acc[j][3]);
        *(float4*)(orow + 32 + 4 * tv) = make_float4(p2.x * z, p2.y * z, p3.x * z, p3.y * z);
    }
}

// ---------------------------------------------------------------------------
extern "C" void kernel_launch(void* const* d_in, const int* in_sizes, int n_in,
                              void* d_out, int out_size) {
    (void)in_sizes; (void)n_in; (void)out_size;
    const float* Q = (const float*)d_in[0];
    const float* K = (const float*)d_in[1];
    const float* V = (const float*)d_in[2];
    float* O = (float*)d_out;

    kv_kernel<<<dim3(SPLIT, NH), 128>>>(K, V);
    reduce_kernel<<<dim3(NH, 4), 256>>>();
    out_kernel<<<dim3(L_LEN / 64, NH), 128>>>(Q, O);
}

// round 11
// speedup vs baseline: 2.0154x; 1.0154x over previous
#include <cuda_runtime.h>
#include <cuda_bf16.h>
#include <cstdint>

typedef unsigned long long ull;

#define N_B    4
#define H_N    8
#define D_K    64
#define S_LEN  4096
#define L_LEN  4096
#define NH     32
#define ROWSTR 512               // floats between consecutive s/l rows
#define SPLIT  32
#define CHUNK  128               // S_LEN / SPLIT
#define STAGE  16
#define NSTG   (CHUNK / STAGE)   // 8

// Persistent scratch (device globals; no runtime allocation).
__device__ float g_partKV[SPLIT * NH * D_K * D_K];   // [split][nh][d][v]
__device__ float g_partKs[SPLIT * NH * D_K];         // [split][nh][d]
__device__ __nv_bfloat16 g_KVhi[NH * D_K * D_K];     // [nh][d][v] bf16 high part
__device__ __nv_bfloat16 g_KVlo[NH * D_K * D_K];     // [nh][d][v] bf16 low part
__device__ float g_Ksum[NH * D_K];                   // [nh][d]

__device__ __forceinline__ float elu1(float x) {
    return x > 0.0f ? x + 1.0f : __expf(x);
}
__device__ __forceinline__ void fma2(ull& d, ull a, ull b) {
    asm("fma.rn.f32x2 %0, %1, %2, %0;" : "+l"(d) : "l"(a), "l"(b));
}
__device__ __forceinline__ ull dup2(float x) {
    ull r; asm("mov.b64 %0, {%1, %1};" : "=l"(r) : "f"(x)); return r;
}
__device__ __forceinline__ float2 unpack2(ull p) {
    float2 r; asm("mov.b64 {%0, %1}, %2;" : "=f"(r.x), "=f"(r.y) : "l"(p)); return r;
}
__device__ __forceinline__ uint32_t smem_u32(const void* p) {
    uint32_t a;
    asm("{ .reg .u64 tmp; cvta.to.shared.u64 tmp, %1; cvt.u32.u64 %0, tmp; }"
        : "=r"(a) : "l"(p));
    return a;
}
__device__ __forceinline__ uint32_t pack_bf16x2(__nv_bfloat16 a, __nv_bfloat16 b) {
    __nv_bfloat162 t = __halves2bfloat162(a, b);
    return *reinterpret_cast<uint32_t*>(&t);
}
// ldmatrix: 4x 8x8 b16 matrices (A operand, row-major tiles).
__device__ __forceinline__ uint4 ldm_x4(uint32_t addr) {
    uint4 r;
    asm volatile("ldmatrix.sync.aligned.m8n8.x4.shared.b16 {%0,%1,%2,%3}, [%4];"
                 : "=r"(r.x), "=r"(r.y), "=r"(r.z), "=r"(r.w) : "r"(addr));
    return r;
}
// ldmatrix transposed (B operand from row-major [k][n] tiles).
__device__ __forceinline__ uint4 ldm_x4t(uint32_t addr) {
    uint4 r;
    asm volatile("ldmatrix.sync.aligned.m8n8.x4.trans.shared.b16 {%0,%1,%2,%3}, [%4];"
                 : "=r"(r.x), "=r"(r.y), "=r"(r.z), "=r"(r.w) : "r"(addr));
    return r;
}
// HMMA bf16: D(16x8,f32) += A(16x16) * B(16x8)
__device__ __forceinline__ void mma_bf16(float* c, uint4 a, uint32_t b0, uint32_t b1) {
    asm volatile(
        "mma.sync.aligned.m16n8k16.row.col.f32.bf16.bf16.f32 "
        "{%0,%1,%2,%3}, {%4,%5,%6,%7}, {%8,%9}, {%0,%1,%2,%3};"
        : "+f"(c[0]), "+f"(c[1]), "+f"(c[2]), "+f"(c[3])
        : "r"(a.x), "r"(a.y), "r"(a.z), "r"(a.w), "r"(b0), "r"(b1));
}

// ---------------------------------------------------------------------------
// Kernel 1: partial KV (stored [d][v]) + partial Ksum (proven R7 version).
// ---------------------------------------------------------------------------
__global__ void __launch_bounds__(128) kv_kernel(const float* __restrict__ Kg,
                                                 const float* __restrict__ Vg) {
    __shared__ __align__(16) float sK[2][STAGE][64];
    __shared__ __align__(16) float sV[2][STAGE][64];
    __shared__ __align__(16) float sRed[8][64];

    const int split = blockIdx.x;
    const int nh    = blockIdx.y;
    const int n     = nh >> 3;
    const int h     = nh & 7;

    const size_t rowbase = ((size_t)n * S_LEN + (size_t)split * CHUNK) * ROWSTR + h * D_K;
    const float* Kb = Kg + rowbase;
    const float* Vb = Vg + rowbase;

    const int t  = threadIdx.x;
    const int td = t >> 3;
    const int tv = t & 7;
    const int lrow = t >> 4;
    const int ck   = t & 15;

    ull acc[4][4];
#pragma unroll
    for (int i = 0; i < 4; i++)
#pragma unroll
        for (int j = 0; j < 4; j++) acc[i][j] = 0ull;
    float ks[4];
#pragma unroll
    for (int i = 0; i < 4; i++) ks[i] = 0.0f;

    const float* kp = Kb + (size_t)lrow * ROWSTR + 4 * ck;
    const float* vp = Vb + (size_t)lrow * ROWSTR + 4 * ck;

    float4 pk0 = *(const float4*)kp;
    float4 pk1 = *(const float4*)(kp + 8 * ROWSTR);
    float4 pv0 = *(const float4*)vp;
    float4 pv1 = *(const float4*)(vp + 8 * ROWSTR);

    auto store_stage = [&](int b) {
        float4 a = pk0, c = pk1;
        a.x = elu1(a.x); a.y = elu1(a.y); a.z = elu1(a.z); a.w = elu1(a.w);
        c.x = elu1(c.x); c.y = elu1(c.y); c.z = elu1(c.z); c.w = elu1(c.w);
        ks[0] += a.x + c.x; ks[1] += a.y + c.y;
        ks[2] += a.z + c.z; ks[3] += a.w + c.w;
        *(float4*)&sK[b][lrow][4 * ck]     = a;
        *(float4*)&sK[b][lrow + 8][4 * ck] = c;
        *(float4*)&sV[b][lrow][4 * ck]     = pv0;
        *(float4*)&sV[b][lrow + 8][4 * ck] = pv1;
    };

    store_stage(0);
    __syncthreads();

    for (int st = 0; st < NSTG; st++) {
        const int cur = st & 1;
        if (st < NSTG - 1) {
            const float* kp2 = kp + (size_t)(st + 1) * STAGE * ROWSTR;
            const float* vp2 = vp + (size_t)(st + 1) * STAGE * ROWSTR;
            pk0 = *(const float4*)kp2;
            pk1 = *(const float4*)(kp2 + 8 * ROWSTR);
            pv0 = *(const float4*)vp2;
            pv1 = *(const float4*)(vp2 + 8 * ROWSTR);
        }

#pragma unroll
        for (int r = 0; r < STAGE; r++) {
            const float4 ka = *(const float4*)&sK[cur][r][4 * td];
            const ulonglong2 va = *(const ulonglong2*)&sV[cur][r][4 * tv];
            const ulonglong2 vb = *(const ulonglong2*)&sV[cur][r][32 + 4 * tv];
            const ull k0 = dup2(ka.x), k1 = dup2(ka.y), k2 = dup2(ka.z), k3 = dup2(ka.w);
            fma2(acc[0][0], k0, va.x); fma2(acc[0][1], k0, va.y); fma2(acc[0][2], k0, vb.x); fma2(acc[0][3], k0, vb.y);
            fma2(acc[1][0], k1, va.x); fma2(acc[1][1], k1, va.y); fma2(acc[1][2], k1, vb.x); fma2(acc[1][3], k1, vb.y);
            fma2(acc[2][0], k2, va.x); fma2(acc[2][1], k2, va.y); fma2(acc[2][2], k2, vb.x); fma2(acc[2][3], k2, vb.y);
            fma2(acc[3][0], k3, va.x); fma2(acc[3][1], k3, va.y); fma2(acc[3][2], k3, vb.x); fma2(acc[3][3], k3, vb.y);
        }

        if (st < NSTG - 1) store_stage(cur ^ 1);
        __syncthreads();
    }

#pragma unroll
    for (int i = 0; i < 4; i++) sRed[lrow][4 * ck + i] = ks[i];
    __syncthreads();
    if (t < 64) {
        float s = 0.0f;
#pragma unroll
        for (int r = 0; r < 8; r++) s += sRed[r][t];
        g_partKs[((size_t)split * NH + nh) * D_K + t] = s;
    }

    float* dst = g_partKV + ((size_t)split * NH + nh) * (D_K * D_K);
#pragma unroll
    for (int di = 0; di < 4; di++) {
        const int d = 4 * td + di;
        const float2 p0 = unpack2(acc[di][0]);
        const float2 p1 = unpack2(acc[di][1]);
        *(float4*)(dst + d * 64 + 4 * tv) = make_float4(p0.x, p0.y, p1.x, p1.y);
        const float2 p2 = unpack2(acc[di][2]);
        const float2 p3 = unpack2(acc[di][3]);
        *(float4*)(dst + d * 64 + 32 + 4 * tv) = make_float4(p2.x, p2.y, p3.x, p3.y);
    }
}

// ---------------------------------------------------------------------------
// Kernel 2: reduce partials -> bf16 hi/lo KV + fp32 Ksum.
// ---------------------------------------------------------------------------
__global__ void __launch_bounds__(256) reduce_kernel() {
    const int nh = blockIdx.x;
    const int i4 = blockIdx.y * 256 + threadIdx.x;   // float4 index 0..1023
    float4 s = make_float4(0.f, 0.f, 0.f, 0.f);
    const float4* base = (const float4*)g_partKV;
#pragma unroll
    for (int p = 0; p < SPLIT; p++) {
        const float4 v = base[((size_t)p * NH + nh) * 1024 + i4];
        s.x += v.x; s.y += v.y; s.z += v.z; s.w += v.w;
    }
    __nv_bfloat16 hx = __float2bfloat16(s.x), hy = __float2bfloat16(s.y);
    __nv_bfloat16 hz = __float2bfloat16(s.z), hw = __float2bfloat16(s.w);
    __nv_bfloat16 lx = __float2bfloat16(s.x - __bfloat162float(hx));
    __nv_bfloat16 ly = __float2bfloat16(s.y - __bfloat162float(hy));
    __nv_bfloat16 lz = __float2bfloat16(s.z - __bfloat162float(hz));
    __nv_bfloat16 lw = __float2bfloat16(s.w - __bfloat162float(hw));
    ((uint2*)(g_KVhi + (size_t)nh * 4096))[i4] =
        make_uint2(pack_bf16x2(hx, hy), pack_bf16x2(hz, hw));
    ((uint2*)(g_KVlo + (size_t)nh * 4096))[i4] =
        make_uint2(pack_bf16x2(lx, ly), pack_bf16x2(lz, lw));

    if (blockIdx.y == 0 && threadIdx.x < 64) {
        float z = 0.0f;
#pragma unroll
        for (int p = 0; p < SPLIT; p++)
            z += g_partKs[((size_t)p * NH + nh) * D_K + threadIdx.x];
        g_Ksum[nh * D_K + threadIdx.x] = z;
    }
}

// ---------------------------------------------------------------------------
// Kernel 3 (HMMA mma.sync): out[l][v] = (Qf[l].KV[:,v]) / (Qf[l].Ksum + eps)
// 128 threads, block tile 64 l x 64 v. bf16-split (hi/lo) 3-term GEMM:
//   D = Ahi*Bhi + Ahi*Blo + Alo*Bhi, fp32 accumulate in registers.
// A = Qf in smem [l][d] stride 72 halves (144B rows -> ldmatrix conflict-free)
// B = KV in smem [d][v] same stride; B fragments via ldmatrix.x4.trans.
// Z computed in fp32 during Q load (16-lane shfl reduction).
// Warp w: m-tile rows 16w..16w+15, all 64 v (8 n-tiles), k = 64 (4 k-tiles).
// ---------------------------------------------------------------------------
#define QS 72   // smem row stride in bf16 halves

__global__ void __launch_bounds__(128) out_kernel(const float* __restrict__ Qg,
                                                  float* __restrict__ Og) {
    __shared__ __align__(16) __nv_bfloat16 sQhi[64][QS];
    __shared__ __align__(16) __nv_bfloat16 sQlo[64][QS];
    __shared__ __align__(16) __nv_bfloat16 sBhi[64][QS];
    __shared__ __align__(16) __nv_bfloat16 sBlo[64][QS];
    __shared__ __align__(16) float sKs[64];
    __shared__ __align__(16) float sZ[64];

    const int nh = blockIdx.y;
    const int l0 = blockIdx.x * 64;
    const int n  = nh >> 3;
    const int h  = nh & 7;
    const int t  = threadIdx.x;

    // Ksum first (needed during Q load for Z).
    if (t < 64) sKs[t] = g_Ksum[nh * D_K + t];

    // Stage KV hi/lo: 64x64 halves each; 4 uint4 per thread per tile.
    {
        const uint4* bh = (const uint4*)(g_KVhi + (size_t)nh * 4096);
        const uint4* bl = (const uint4*)(g_KVlo + (size_t)nh * 4096);
#pragma unroll
        for (int i = 0; i < 4; i++) {
            const int idx = i * 128 + t;          // uint4 = 8 halves; 512 total
            const int row = idx >> 3, cg = idx & 7;
            *(uint4*)&sBhi[row][8 * cg] = bh[idx];
            *(uint4*)&sBlo[row][8 * cg] = bl[idx];
        }
    }
    __syncthreads();

    // Load + feature-map Q tile (64 x 64), compute Z in fp32, split to bf16.
    {
        const int qr = t >> 4;                // 0..7
        const int qc = (t & 15) * 4;          // col group
        const float* Qb = Qg + ((size_t)n * L_LEN + l0) * ROWSTR + h * D_K;
        float zp[8];
#pragma unroll
        for (int p = 0; p < 8; p++) zp[p] = 0.0f;
#pragma unroll
        for (int p = 0; p < 8; p++) {
            const int l = p * 8 + qr;
            float4 q = *(const float4*)(Qb + (size_t)l * ROWSTR + qc);
            const float f0 = elu1(q.x), f1 = elu1(q.y), f2 = elu1(q.z), f3 = elu1(q.w);
            zp[p] = f0 * sKs[qc] + f1 * sKs[qc + 1] + f2 * sKs[qc + 2] + f3 * sKs[qc + 3];
            const __nv_bfloat16 h0 = __float2bfloat16(f0), h1 = __float2bfloat16(f1);
            const __nv_bfloat16 h2 = __float2bfloat16(f2), h3 = __float2bfloat16(f3);
            *(uint2*)&sQhi[l][qc] = make_uint2(pack_bf16x2(h0, h1), pack_bf16x2(h2, h3));
            *(uint2*)&sQlo[l][qc] = make_uint2(
                pack_bf16x2(__float2bfloat16(f0 - __bfloat162float(h0)),
                            __float2bfloat16(f1 - __bfloat162float(h1))),
                pack_bf16x2(__float2bfloat16(f2 - __bfloat162float(h2)),
                            __float2bfloat16(f3 - __bfloat162float(h3))));
        }
        // Reduce each zp over the 16 threads sharing qr (lanes of width-16 group).
#pragma unroll
        for (int p = 0; p < 8; p++) {
#pragma unroll
            for (int o = 8; o > 0; o >>= 1)
                zp[p] += __shfl_xor_sync(0xFFFFFFFFu, zp[p], o, 16);
        }
        const int c = t & 15;
        if (c < 8) sZ[c * 8 + qr] = 1.0f / (zp[c] + 1e-6f);
    }
    __syncthreads();

    // MMA phase: warp w handles rows 16w..16w+15.
    const int w    = t >> 5;
    const int lane = t & 31;
    const int L    = 16 * w;

    // ldmatrix lane addressing (A, row-major tiles):
    //   lanes 0-7: rows L+0..7 col d | 8-15: rows L+8..15 col d
    //   16-23: rows L+0..7 col d+8   | 24-31: rows L+8..15 col d+8
    const int arow = L + (lane & 7) + ((lane >> 3) & 1) * 8;
    const int acol = ((lane >> 4) & 1) * 8;
    // B (trans, [k][n] tiles): lanes 0-7 rows 16k+0..7 col 8n | 8-15 rows +8
    //   16-23: rows 16k+0..7 col 8n+8 | 24-31: rows +8 col 8n+8
    const int brow = (lane & 7) + ((lane >> 3) & 1) * 8;
    const int bcol = ((lane >> 4) & 1) * 8;

    float acc[8][4];
#pragma unroll
    for (int nt = 0; nt < 8; nt++)
#pragma unroll
        for (int i = 0; i < 4; i++) acc[nt][i] = 0.0f;

    const uint32_t aQhi = smem_u32(&sQhi[arow][acol]);
    const uint32_t aQlo = smem_u32(&sQlo[arow][acol]);
    const uint32_t aBhi = smem_u32(&sBhi[brow][bcol]);
    const uint32_t aBlo = smem_u32(&sBlo[brow][bcol]);

#pragma unroll
    for (int term = 0; term < 3; term++) {
        const uint32_t abase = (term == 2) ? aQlo : aQhi;
        const uint32_t bbase = (term == 1) ? aBlo : aBhi;
#pragma unroll
        for (int k = 0; k < 4; k++) {
            const uint4 a = ldm_x4(abase + (uint32_t)(16 * k) * 2);
#pragma unroll
            for (int np = 0; np < 4; np++) {
                // n-pair np covers n-tiles 2np, 2np+1 (cols 16np, 16np+8)
                const uint4 b = ldm_x4t(bbase +
                    ((uint32_t)(16 * k) * QS + (uint32_t)(16 * np)) * 2);
                mma_bf16(acc[2 * np],     a, b.x, b.y);
                mma_bf16(acc[2 * np + 1], a, b.z, b.w);
            }
        }
    }

    // Epilogue: fragment rows r0 = L + lane/4, r1 = r0 + 8; cols 8nt + 2(lane%4).
    {
        const int r0 = L + (lane >> 2);
        const int r1 = r0 + 8;
        const float z0 = sZ[r0], z1 = sZ[r1];
        float* o0 = Og + ((size_t)(n * L_LEN + l0 + r0)) * ROWSTR + h * D_K;
        float* o1 = Og + ((size_t)(n * L_LEN + l0 + r1)) * ROWSTR + h * D_K;
        const int cb = 2 * (lane & 3);
#pragma unroll
        for (int nt = 0; nt < 8; nt++) {
            *(float2*)(o0 + 8 * nt + cb) = make_float2(acc[nt][0] * z0, acc[nt][1] * z0);
            *(float2*)(o1 + 8 * nt + cb) = make_float2(acc[nt][2] * z1, acc[nt][3] * z1);
        }
    }
}

// ---------------------------------------------------------------------------
extern "C" void kernel_launch(void* const* d_in, const int* in_sizes, int n_in,
                              void* d_out, int out_size) {
    (void)in_sizes; (void)n_in; (void)out_size;
    const float* Q = (const float*)d_in[0];
    const float* K = (const float*)d_in[1];
    const float* V = (const float*)d_in[2];
    float* O = (float*)d_out;

    kv_kernel<<<dim3(SPLIT, NH), 128>>>(K, V);
    reduce_kernel<<<dim3(NH, 4), 256>>>();
    out_kernel<<<dim3(L_LEN / 64, NH), 128>>>(Q, O);
}

// round 12
// speedup vs baseline: 2.3565x; 1.1692x over previous
#include <cuda_runtime.h>
#include <cuda_bf16.h>
#include <cstdint>

typedef unsigned long long ull;

#define N_B    4
#define H_N    8
#define D_K    64
#define S_LEN  4096
#define L_LEN  4096
#define NH     32
#define ROWSTR 512               // floats between consecutive s/l rows
#define SPLIT  16
#define CHUNK  256               // S_LEN / SPLIT
#define KSTAGE 32                // s-rows per double-buffered stage
#define NSTG   (CHUNK / KSTAGE)  // 8
#define QS     72                // smem row stride in bf16 halves (144B)

// Persistent scratch (device globals; no runtime allocation).
__device__ float g_partKV[SPLIT * NH * D_K * D_K];   // [split][nh][d][v]
__device__ float g_partKs[SPLIT * NH * D_K];         // [split][nh][d]
__device__ __nv_bfloat16 g_KVhi[NH * D_K * D_K];     // [nh][d][v] bf16 high part
__device__ __nv_bfloat16 g_KVlo[NH * D_K * D_K];     // [nh][d][v] bf16 low part
__device__ float g_Ksum[NH * D_K];                   // [nh][d]

__device__ __forceinline__ float elu1(float x) {
    return x > 0.0f ? x + 1.0f : __expf(x);
}
__device__ __forceinline__ uint32_t smem_u32(const void* p) {
    uint32_t a;
    asm("{ .reg .u64 tmp; cvta.to.shared.u64 tmp, %1; cvt.u32.u64 %0, tmp; }"
        : "=r"(a) : "l"(p));
    return a;
}
__device__ __forceinline__ uint32_t pack_bf16x2(__nv_bfloat16 a, __nv_bfloat16 b) {
    __nv_bfloat162 t = __halves2bfloat162(a, b);
    return *reinterpret_cast<uint32_t*>(&t);
}
__device__ __forceinline__ uint4 ldm_x4(uint32_t addr) {
    uint4 r;
    asm volatile("ldmatrix.sync.aligned.m8n8.x4.shared.b16 {%0,%1,%2,%3}, [%4];"
                 : "=r"(r.x), "=r"(r.y), "=r"(r.z), "=r"(r.w) : "r"(addr));
    return r;
}
__device__ __forceinline__ uint4 ldm_x4t(uint32_t addr) {
    uint4 r;
    asm volatile("ldmatrix.sync.aligned.m8n8.x4.trans.shared.b16 {%0,%1,%2,%3}, [%4];"
                 : "=r"(r.x), "=r"(r.y), "=r"(r.z), "=r"(r.w) : "r"(addr));
    return r;
}
__device__ __forceinline__ void mma_bf16(float* c, uint4 a, uint32_t b0, uint32_t b1) {
    asm volatile(
        "mma.sync.aligned.m16n8k16.row.col.f32.bf16.bf16.f32 "
        "{%0,%1,%2,%3}, {%4,%5,%6,%7}, {%8,%9}, {%0,%1,%2,%3};"
        : "+f"(c[0]), "+f"(c[1]), "+f"(c[2]), "+f"(c[3])
        : "r"(a.x), "r"(a.y), "r"(a.z), "r"(a.w), "r"(b0), "r"(b1));
}

// ---------------------------------------------------------------------------
// Kernel 1 (HMMA): partial KV[d][v] += K^T V over an S-chunk, + partial Ksum.
// A = elu(K) split hi/lo in smem [s][d]; fragments via ldmatrix.x4.trans
//     (A tile (m=d, k=s): lanes 0-7 -> s0-7/d, 8-15 -> s0-7/d+8,
//      16-23 -> s8-15/d, 24-31 -> s8-15/d+8).
// B = V split hi/lo in smem [s][v]; same proven trans pattern as out_kernel.
// 3-term bf16-split: Khi*Vhi + Khi*Vlo + Klo*Vhi, fp32 accumulate.
// 128 thr; warp w owns d rows 16w..16w+15, all 64 v. 8 x 32-row stages, 2-buf.
// ---------------------------------------------------------------------------
__global__ void __launch_bounds__(128) kv_kernel(const float* __restrict__ Kg,
                                                 const float* __restrict__ Vg) {
    __shared__ __align__(16) __nv_bfloat16 sKhi[2][KSTAGE][QS];
    __shared__ __align__(16) __nv_bfloat16 sKlo[2][KSTAGE][QS];
    __shared__ __align__(16) __nv_bfloat16 sVhi[2][KSTAGE][QS];
    __shared__ __align__(16) __nv_bfloat16 sVlo[2][KSTAGE][QS];
    __shared__ __align__(16) float sRed[KSTAGE][64];

    const int split = blockIdx.x;
    const int nh    = blockIdx.y;
    const int n     = nh >> 3;
    const int h     = nh & 7;

    const size_t rowbase = ((size_t)n * S_LEN + (size_t)split * CHUNK) * ROWSTR + h * D_K;
    const float* Kb = Kg + rowbase;
    const float* Vb = Vg + rowbase;

    const int t  = threadIdx.x;
    const int lr = t >> 2;               // loader row 0..31
    const int c0 = (t & 3) * 16;         // loader col base (16 cols per thread)

    const float* kp = Kb + (size_t)lr * ROWSTR + c0;
    const float* vp = Vb + (size_t)lr * ROWSTR + c0;

    float ks[16];
#pragma unroll
    for (int i = 0; i < 16; i++) ks[i] = 0.0f;

    float4 pk[4], pv[4];
#pragma unroll
    for (int i = 0; i < 4; i++) {
        pk[i] = *(const float4*)(kp + 4 * i);
        pv[i] = *(const float4*)(vp + 4 * i);
    }

    auto store_stage = [&](int b) {
#pragma unroll
        for (int i = 0; i < 4; i++) {
            const float f0 = elu1(pk[i].x), f1 = elu1(pk[i].y);
            const float f2 = elu1(pk[i].z), f3 = elu1(pk[i].w);
            ks[4 * i] += f0; ks[4 * i + 1] += f1;
            ks[4 * i + 2] += f2; ks[4 * i + 3] += f3;
            const __nv_bfloat16 h0 = __float2bfloat16(f0), h1 = __float2bfloat16(f1);
            const __nv_bfloat16 h2 = __float2bfloat16(f2), h3 = __float2bfloat16(f3);
            *(uint2*)&sKhi[b][lr][c0 + 4 * i] =
                make_uint2(pack_bf16x2(h0, h1), pack_bf16x2(h2, h3));
            *(uint2*)&sKlo[b][lr][c0 + 4 * i] = make_uint2(
                pack_bf16x2(__float2bfloat16(f0 - __bfloat162float(h0)),
                            __float2bfloat16(f1 - __bfloat162float(h1))),
                pack_bf16x2(__float2bfloat16(f2 - __bfloat162float(h2)),
                            __float2bfloat16(f3 - __bfloat162float(h3))));
            const float g0 = pv[i].x, g1 = pv[i].y, g2 = pv[i].z, g3 = pv[i].w;
            const __nv_bfloat16 e0 = __float2bfloat16(g0), e1 = __float2bfloat16(g1);
            const __nv_bfloat16 e2 = __float2bfloat16(g2), e3 = __float2bfloat16(g3);
            *(uint2*)&sVhi[b][lr][c0 + 4 * i] =
                make_uint2(pack_bf16x2(e0, e1), pack_bf16x2(e2, e3));
            *(uint2*)&sVlo[b][lr][c0 + 4 * i] = make_uint2(
                pack_bf16x2(__float2bfloat16(g0 - __bfloat162float(e0)),
                            __float2bfloat16(g1 - __bfloat162float(e1))),
                pack_bf16x2(__float2bfloat16(g2 - __bfloat162float(e2)),
                            __float2bfloat16(g3 - __bfloat162float(e3))));
        }
    };

    store_stage(0);
    __syncthreads();

    // MMA lane addressing.
    const int w    = t >> 5;
    const int lane = t & 31;
    // A (trans from [s][d]): see header comment.
    const int arow = (lane & 7) + ((lane >> 4) & 1) * 8;
    const int acol = 16 * w + ((lane >> 3) & 1) * 8;
    // B (trans from [s][v]) — proven pattern.
    const int brow = (lane & 7) + ((lane >> 3) & 1) * 8;
    const int bcol = ((lane >> 4) & 1) * 8;

    const uint32_t aKhi = smem_u32(&sKhi[0][arow][acol]);
    const uint32_t aKlo = smem_u32(&sKlo[0][arow][acol]);
    const uint32_t aVhi = smem_u32(&sVhi[0][brow][bcol]);
    const uint32_t aVlo = smem_u32(&sVlo[0][brow][bcol]);
    const uint32_t bufB = KSTAGE * QS * 2;   // bytes per buffer
    const uint32_t ktB  = 16 * QS * 2;       // bytes per 16-row k-step

    float acc[8][4];
#pragma unroll
    for (int nt = 0; nt < 8; nt++)
#pragma unroll
        for (int i = 0; i < 4; i++) acc[nt][i] = 0.0f;

    for (int st = 0; st < NSTG; st++) {
        const int cur = st & 1;
        if (st < NSTG - 1) {
            const float* kp2 = kp + (size_t)(st + 1) * KSTAGE * ROWSTR;
            const float* vp2 = vp + (size_t)(st + 1) * KSTAGE * ROWSTR;
#pragma unroll
            for (int i = 0; i < 4; i++) {
                pk[i] = *(const float4*)(kp2 + 4 * i);
                pv[i] = *(const float4*)(vp2 + 4 * i);
            }
        }

        const uint32_t bo = cur * bufB;
#pragma unroll
        for (int k = 0; k < 2; k++) {
#pragma unroll
            for (int term = 0; term < 3; term++) {
                const uint32_t abase = ((term == 2) ? aKlo : aKhi) + bo + k * ktB;
                const uint32_t bbase = ((term == 1) ? aVlo : aVhi) + bo + k * ktB;
                const uint4 a = ldm_x4t(abase);
#pragma unroll
                for (int np = 0; np < 4; np++) {
                    const uint4 b = ldm_x4t(bbase + (uint32_t)(16 * np) * 2);
                    mma_bf16(acc[2 * np],     a, b.x, b.y);
                    mma_bf16(acc[2 * np + 1], a, b.z, b.w);
                }
            }
        }

        if (st < NSTG - 1) store_stage(cur ^ 1);
        __syncthreads();
    }

    // Ksum: each thread wrote partial sums for its 16 cols over all its rows.
#pragma unroll
    for (int i = 0; i < 16; i++) sRed[lr][c0 + i] = ks[i];
    __syncthreads();
    if (t < 64) {
        float s = 0.0f;
#pragma unroll
        for (int r = 0; r < KSTAGE; r++) s += sRed[r][t];
        g_partKs[((size_t)split * NH + nh) * D_K + t] = s;
    }

    // Store partial KV fragments: rows d = 16w + lane/4 (+8), cols 8nt+2(lane%4).
    {
        float* dst = g_partKV + ((size_t)split * NH + nh) * (D_K * D_K);
        const int r0 = 16 * w + (lane >> 2);
        const int r1 = r0 + 8;
        const int cb = 2 * (lane & 3);
#pragma unroll
        for (int nt = 0; nt < 8; nt++) {
            *(float2*)(dst + r0 * 64 + 8 * nt + cb) = make_float2(acc[nt][0], acc[nt][1]);
            *(float2*)(dst + r1 * 64 + 8 * nt + cb) = make_float2(acc[nt][2], acc[nt][3]);
        }
    }
}

// ---------------------------------------------------------------------------
// Kernel 2: reduce partials -> bf16 hi/lo KV + fp32 Ksum.
// ---------------------------------------------------------------------------
__global__ void __launch_bounds__(256) reduce_kernel() {
    const int nh = blockIdx.x;
    const int i4 = blockIdx.y * 256 + threadIdx.x;   // float4 index 0..1023
    float4 s = make_float4(0.f, 0.f, 0.f, 0.f);
    const float4* base = (const float4*)g_partKV;
#pragma unroll
    for (int p = 0; p < SPLIT; p++) {
        const float4 v = base[((size_t)p * NH + nh) * 1024 + i4];
        s.x += v.x; s.y += v.y; s.z += v.z; s.w += v.w;
    }
    __nv_bfloat16 hx = __float2bfloat16(s.x), hy = __float2bfloat16(s.y);
    __nv_bfloat16 hz = __float2bfloat16(s.z), hw = __float2bfloat16(s.w);
    __nv_bfloat16 lx = __float2bfloat16(s.x - __bfloat162float(hx));
    __nv_bfloat16 ly = __float2bfloat16(s.y - __bfloat162float(hy));
    __nv_bfloat16 lz = __float2bfloat16(s.z - __bfloat162float(hz));
    __nv_bfloat16 lw = __float2bfloat16(s.w - __bfloat162float(hw));
    ((uint2*)(g_KVhi + (size_t)nh * 4096))[i4] =
        make_uint2(pack_bf16x2(hx, hy), pack_bf16x2(hz, hw));
    ((uint2*)(g_KVlo + (size_t)nh * 4096))[i4] =
        make_uint2(pack_bf16x2(lx, ly), pack_bf16x2(lz, lw));

    if (blockIdx.y == 0 && threadIdx.x < 64) {
        float z = 0.0f;
#pragma unroll
        for (int p = 0; p < SPLIT; p++)
            z += g_partKs[((size_t)p * NH + nh) * D_K + threadIdx.x];
        g_Ksum[nh * D_K + threadIdx.x] = z;
    }
}

// ---------------------------------------------------------------------------
// Kernel 3 (HMMA, proven R11): out[l][v] = (Qf[l].KV[:,v]) * Z[l].
// ---------------------------------------------------------------------------
__global__ void __launch_bounds__(128) out_kernel(const float* __restrict__ Qg,
                                                  float* __restrict__ Og) {
    __shared__ __align__(16) __nv_bfloat16 sQhi[64][QS];
    __shared__ __align__(16) __nv_bfloat16 sQlo[64][QS];
    __shared__ __align__(16) __nv_bfloat16 sBhi[64][QS];
    __shared__ __align__(16) __nv_bfloat16 sBlo[64][QS];
    __shared__ __align__(16) float sKs[64];
    __shared__ __align__(16) float sZ[64];

    const int nh = blockIdx.y;
    const int l0 = blockIdx.x * 64;
    const int n  = nh >> 3;
    const int h  = nh & 7;
    const int t  = threadIdx.x;

    if (t < 64) sKs[t] = g_Ksum[nh * D_K + t];

    {
        const uint4* bh = (const uint4*)(g_KVhi + (size_t)nh * 4096);
        const uint4* bl = (const uint4*)(g_KVlo + (size_t)nh * 4096);
#pragma unroll
        for (int i = 0; i < 4; i++) {
            const int idx = i * 128 + t;
            const int row = idx >> 3, cg = idx & 7;
            *(uint4*)&sBhi[row][8 * cg] = bh[idx];
            *(uint4*)&sBlo[row][8 * cg] = bl[idx];
        }
    }
    __syncthreads();

    {
        const int qr = t >> 4;
        const int qc = (t & 15) * 4;
        const float* Qb = Qg + ((size_t)n * L_LEN + l0) * ROWSTR + h * D_K;
        float zp[8];
#pragma unroll
        for (int p = 0; p < 8; p++) zp[p] = 0.0f;
#pragma unroll
        for (int p = 0; p < 8; p++) {
            const int l = p * 8 + qr;
            float4 q = *(const float4*)(Qb + (size_t)l * ROWSTR + qc);
            const float f0 = elu1(q.x), f1 = elu1(q.y), f2 = elu1(q.z), f3 = elu1(q.w);
            zp[p] = f0 * sKs[qc] + f1 * sKs[qc + 1] + f2 * sKs[qc + 2] + f3 * sKs[qc + 3];
            const __nv_bfloat16 h0 = __float2bfloat16(f0), h1 = __float2bfloat16(f1);
            const __nv_bfloat16 h2 = __float2bfloat16(f2), h3 = __float2bfloat16(f3);
            *(uint2*)&sQhi[l][qc] = make_uint2(pack_bf16x2(h0, h1), pack_bf16x2(h2, h3));
            *(uint2*)&sQlo[l][qc] = make_uint2(
                pack_bf16x2(__float2bfloat16(f0 - __bfloat162float(h0)),
                            __float2bfloat16(f1 - __bfloat162float(h1))),
                pack_bf16x2(__float2bfloat16(f2 - __bfloat162float(h2)),
                            __float2bfloat16(f3 - __bfloat162float(h3))));
        }
#pragma unroll
        for (int p = 0; p < 8; p++) {
#pragma unroll
            for (int o = 8; o > 0; o >>= 1)
                zp[p] += __shfl_xor_sync(0xFFFFFFFFu, zp[p], o, 16);
        }
        const int c = t & 15;
        if (c < 8) sZ[c * 8 + qr] = 1.0f / (zp[c] + 1e-6f);
    }
    __syncthreads();

    const int w    = t >> 5;
    const int lane = t & 31;
    const int L    = 16 * w;

    const int arow = L + (lane & 7) + ((lane >> 3) & 1) * 8;
    const int acol = ((lane >> 4) & 1) * 8;
    const int brow = (lane & 7) + ((lane >> 3) & 1) * 8;
    const int bcol = ((lane >> 4) & 1) * 8;

    float acc[8][4];
#pragma unroll
    for (int nt = 0; nt < 8; nt++)
#pragma unroll
        for (int i = 0; i < 4; i++) acc[nt][i] = 0.0f;

    const uint32_t aQhi = smem_u32(&sQhi[arow][acol]);
    const uint32_t aQlo = smem_u32(&sQlo[arow][acol]);
    const uint32_t aBhi = smem_u32(&sBhi[brow][bcol]);
    const uint32_t aBlo = smem_u32(&sBlo[brow][bcol]);

#pragma unroll
    for (int term = 0; term < 3; term++) {
        const uint32_t abase = (term == 2) ? aQlo : aQhi;
        const uint32_t bbase = (term == 1) ? aBlo : aBhi;
#pragma unroll
        for (int k = 0; k < 4; k++) {
            const uint4 a = ldm_x4(abase + (uint32_t)(16 * k) * 2);
#pragma unroll
            for (int np = 0; np < 4; np++) {
                const uint4 b = ldm_x4t(bbase +
                    ((uint32_t)(16 * k) * QS + (uint32_t)(16 * np)) * 2);
                mma_bf16(acc[2 * np],     a, b.x, b.y);
                mma_bf16(acc[2 * np + 1], a, b.z, b.w);
            }
        }
    }

    {
        const int r0 = L + (lane >> 2);
        const int r1 = r0 + 8;
        const float z0 = sZ[r0], z1 = sZ[r1];
        float* o0 = Og + ((size_t)(n * L_LEN + l0 + r0)) * ROWSTR + h * D_K;
        float* o1 = Og + ((size_t)(n * L_LEN + l0 + r1)) * ROWSTR + h * D_K;
        const int cb = 2 * (lane & 3);
#pragma unroll
        for (int nt = 0; nt < 8; nt++) {
            *(float2*)(o0 + 8 * nt + cb) = make_float2(acc[nt][0] * z0, acc[nt][1] * z0);
            *(float2*)(o1 + 8 * nt + cb) = make_float2(acc[nt][2] * z1, acc[nt][3] * z1);
        }
    }
}

// ---------------------------------------------------------------------------
extern "C" void kernel_launch(void* const* d_in, const int* in_sizes, int n_in,
                              void* d_out, int out_size) {
    (void)in_sizes; (void)n_in; (void)out_size;
    const float* Q = (const float*)d_in[0];
    const float* K = (const float*)d_in[1];
    const float* V = (const float*)d_in[2];
    float* O = (float*)d_out;

    kv_kernel<<<dim3(SPLIT, NH), 128>>>(K, V);
    reduce_kernel<<<dim3(NH, 4), 256>>>();
    out_kernel<<<dim3(L_LEN / 64, NH), 128>>>(Q, O);
}

// round 13
// speedup vs baseline: 2.5226x; 1.0705x over previous
#include <cuda_runtime.h>
#include <cuda_bf16.h>
#include <cstdint>

typedef unsigned long long ull;

#define N_B    4
#define H_N    8
#define D_K    64
#define S_LEN  4096
#define L_LEN  4096
#define NH     32
#define ROWSTR 512               // floats between consecutive s/l rows
#define SPLIT  16
#define CHUNK  256               // S_LEN / SPLIT
#define KSTAGE 32                // s-rows per double-buffered stage
#define NSTG   (CHUNK / KSTAGE)  // 8
#define QS     72                // smem row stride in bf16 halves (144B)

// Persistent scratch (device globals; no runtime allocation).
__device__ float g_partKV[SPLIT * NH * D_K * D_K];   // [split][nh][d][v]
__device__ float g_partKs[SPLIT * NH * D_K];         // [split][nh][d]
__device__ __nv_bfloat16 g_KVhi[NH * D_K * D_K];     // [nh][d][v] bf16 high part
__device__ __nv_bfloat16 g_KVlo[NH * D_K * D_K];     // [nh][d][v] bf16 low part
__device__ float g_Ksum[NH * D_K];                   // [nh][d]

__device__ __forceinline__ float elu1(float x) {
    return x > 0.0f ? x + 1.0f : __expf(x);
}
__device__ __forceinline__ uint32_t smem_u32(const void* p) {
    uint32_t a;
    asm("{ .reg .u64 tmp; cvta.to.shared.u64 tmp, %1; cvt.u32.u64 %0, tmp; }"
        : "=r"(a) : "l"(p));
    return a;
}
__device__ __forceinline__ uint32_t pack_bf16x2(__nv_bfloat16 a, __nv_bfloat16 b) {
    __nv_bfloat162 t = __halves2bfloat162(a, b);
    return *reinterpret_cast<uint32_t*>(&t);
}
__device__ __forceinline__ uint4 ldm_x4(uint32_t addr) {
    uint4 r;
    asm volatile("ldmatrix.sync.aligned.m8n8.x4.shared.b16 {%0,%1,%2,%3}, [%4];"
                 : "=r"(r.x), "=r"(r.y), "=r"(r.z), "=r"(r.w) : "r"(addr));
    return r;
}
__device__ __forceinline__ uint4 ldm_x4t(uint32_t addr) {
    uint4 r;
    asm volatile("ldmatrix.sync.aligned.m8n8.x4.trans.shared.b16 {%0,%1,%2,%3}, [%4];"
                 : "=r"(r.x), "=r"(r.y), "=r"(r.z), "=r"(r.w) : "r"(addr));
    return r;
}
__device__ __forceinline__ void mma_bf16(float* c, uint4 a, uint32_t b0, uint32_t b1) {
    asm volatile(
        "mma.sync.aligned.m16n8k16.row.col.f32.bf16.bf16.f32 "
        "{%0,%1,%2,%3}, {%4,%5,%6,%7}, {%8,%9}, {%0,%1,%2,%3};"
        : "+f"(c[0]), "+f"(c[1]), "+f"(c[2]), "+f"(c[3])
        : "r"(a.x), "r"(a.y), "r"(a.z), "r"(a.w), "r"(b0), "r"(b1));
}

// ---------------------------------------------------------------------------
// Kernel 1 (HMMA): partial KV[d][v] += K^T V over an S-chunk, + partial Ksum.
// 3-term bf16-split with HOISTED fragments: per k-step load a_hi/a_lo once,
// per n-pair load b_hi/b_lo once, then 6 mma from registers.
// 10 ldmatrix per k-step (was 15) -> ~33% less smem read traffic.
// ---------------------------------------------------------------------------
__global__ void __launch_bounds__(128) kv_kernel(const float* __restrict__ Kg,
                                                 const float* __restrict__ Vg) {
    __shared__ __align__(16) __nv_bfloat16 sKhi[2][KSTAGE][QS];
    __shared__ __align__(16) __nv_bfloat16 sKlo[2][KSTAGE][QS];
    __shared__ __align__(16) __nv_bfloat16 sVhi[2][KSTAGE][QS];
    __shared__ __align__(16) __nv_bfloat16 sVlo[2][KSTAGE][QS];
    __shared__ __align__(16) float sRed[KSTAGE][64];

    const int split = blockIdx.x;
    const int nh    = blockIdx.y;
    const int n     = nh >> 3;
    const int h     = nh & 7;

    const size_t rowbase = ((size_t)n * S_LEN + (size_t)split * CHUNK) * ROWSTR + h * D_K;
    const float* Kb = Kg + rowbase;
    const float* Vb = Vg + rowbase;

    const int t  = threadIdx.x;
    const int lr = t >> 2;               // loader row 0..31
    const int c0 = (t & 3) * 16;         // loader col base (16 cols per thread)

    const float* kp = Kb + (size_t)lr * ROWSTR + c0;
    const float* vp = Vb + (size_t)lr * ROWSTR + c0;

    float ks[16];
#pragma unroll
    for (int i = 0; i < 16; i++) ks[i] = 0.0f;

    float4 pk[4], pv[4];
#pragma unroll
    for (int i = 0; i < 4; i++) {
        pk[i] = *(const float4*)(kp + 4 * i);
        pv[i] = *(const float4*)(vp + 4 * i);
    }

    auto store_stage = [&](int b) {
#pragma unroll
        for (int i = 0; i < 4; i++) {
            const float f0 = elu1(pk[i].x), f1 = elu1(pk[i].y);
            const float f2 = elu1(pk[i].z), f3 = elu1(pk[i].w);
            ks[4 * i] += f0; ks[4 * i + 1] += f1;
            ks[4 * i + 2] += f2; ks[4 * i + 3] += f3;
            const __nv_bfloat16 h0 = __float2bfloat16(f0), h1 = __float2bfloat16(f1);
            const __nv_bfloat16 h2 = __float2bfloat16(f2), h3 = __float2bfloat16(f3);
            *(uint2*)&sKhi[b][lr][c0 + 4 * i] =
                make_uint2(pack_bf16x2(h0, h1), pack_bf16x2(h2, h3));
            *(uint2*)&sKlo[b][lr][c0 + 4 * i] = make_uint2(
                pack_bf16x2(__float2bfloat16(f0 - __bfloat162float(h0)),
                            __float2bfloat16(f1 - __bfloat162float(h1))),
                pack_bf16x2(__float2bfloat16(f2 - __bfloat162float(h2)),
                            __float2bfloat16(f3 - __bfloat162float(h3))));
            const float g0 = pv[i].x, g1 = pv[i].y, g2 = pv[i].z, g3 = pv[i].w;
            const __nv_bfloat16 e0 = __float2bfloat16(g0), e1 = __float2bfloat16(g1);
            const __nv_bfloat16 e2 = __float2bfloat16(g2), e3 = __float2bfloat16(g3);
            *(uint2*)&sVhi[b][lr][c0 + 4 * i] =
                make_uint2(pack_bf16x2(e0, e1), pack_bf16x2(e2, e3));
            *(uint2*)&sVlo[b][lr][c0 + 4 * i] = make_uint2(
                pack_bf16x2(__float2bfloat16(g0 - __bfloat162float(e0)),
                            __float2bfloat16(g1 - __bfloat162float(e1))),
                pack_bf16x2(__float2bfloat16(g2 - __bfloat162float(e2)),
                            __float2bfloat16(g3 - __bfloat162float(e3))));
        }
    };

    store_stage(0);
    __syncthreads();

    // MMA lane addressing (verified in R12).
    const int w    = t >> 5;
    const int lane = t & 31;
    const int arow = (lane & 7) + ((lane >> 4) & 1) * 8;
    const int acol = 16 * w + ((lane >> 3) & 1) * 8;
    const int brow = (lane & 7) + ((lane >> 3) & 1) * 8;
    const int bcol = ((lane >> 4) & 1) * 8;

    const uint32_t aKhi = smem_u32(&sKhi[0][arow][acol]);
    const uint32_t aKlo = smem_u32(&sKlo[0][arow][acol]);
    const uint32_t aVhi = smem_u32(&sVhi[0][brow][bcol]);
    const uint32_t aVlo = smem_u32(&sVlo[0][brow][bcol]);
    const uint32_t bufB = KSTAGE * QS * 2;   // bytes per buffer
    const uint32_t ktB  = 16 * QS * 2;       // bytes per 16-row k-step

    float acc[8][4];
#pragma unroll
    for (int nt = 0; nt < 8; nt++)
#pragma unroll
        for (int i = 0; i < 4; i++) acc[nt][i] = 0.0f;

    for (int st = 0; st < NSTG; st++) {
        const int cur = st & 1;
        if (st < NSTG - 1) {
            const float* kp2 = kp + (size_t)(st + 1) * KSTAGE * ROWSTR;
            const float* vp2 = vp + (size_t)(st + 1) * KSTAGE * ROWSTR;
#pragma unroll
            for (int i = 0; i < 4; i++) {
                pk[i] = *(const float4*)(kp2 + 4 * i);
                pv[i] = *(const float4*)(vp2 + 4 * i);
            }
        }

        const uint32_t bo = cur * bufB;
#pragma unroll
        for (int k = 0; k < 2; k++) {
            const uint4 ahi = ldm_x4t(aKhi + bo + k * ktB);
            const uint4 alo = ldm_x4t(aKlo + bo + k * ktB);
#pragma unroll
            for (int np = 0; np < 4; np++) {
                const uint32_t boff = bo + k * ktB + (uint32_t)(16 * np) * 2;
                const uint4 bhi = ldm_x4t(aVhi + boff);
                const uint4 blo = ldm_x4t(aVlo + boff);
                mma_bf16(acc[2 * np],     ahi, bhi.x, bhi.y);
                mma_bf16(acc[2 * np],     ahi, blo.x, blo.y);
                mma_bf16(acc[2 * np],     alo, bhi.x, bhi.y);
                mma_bf16(acc[2 * np + 1], ahi, bhi.z, bhi.w);
                mma_bf16(acc[2 * np + 1], ahi, blo.z, blo.w);
                mma_bf16(acc[2 * np + 1], alo, bhi.z, bhi.w);
            }
        }

        if (st < NSTG - 1) store_stage(cur ^ 1);
        __syncthreads();
    }

    // Ksum: each thread wrote partial sums for its 16 cols over all its rows.
#pragma unroll
    for (int i = 0; i < 16; i++) sRed[lr][c0 + i] = ks[i];
    __syncthreads();
    if (t < 64) {
        float s = 0.0f;
#pragma unroll
        for (int r = 0; r < KSTAGE; r++) s += sRed[r][t];
        g_partKs[((size_t)split * NH + nh) * D_K + t] = s;
    }

    // Store partial KV fragments.
    {
        float* dst = g_partKV + ((size_t)split * NH + nh) * (D_K * D_K);
        const int r0 = 16 * w + (lane >> 2);
        const int r1 = r0 + 8;
        const int cb = 2 * (lane & 3);
#pragma unroll
        for (int nt = 0; nt < 8; nt++) {
            *(float2*)(dst + r0 * 64 + 8 * nt + cb) = make_float2(acc[nt][0], acc[nt][1]);
            *(float2*)(dst + r1 * 64 + 8 * nt + cb) = make_float2(acc[nt][2], acc[nt][3]);
        }
    }
}

// ---------------------------------------------------------------------------
// Kernel 2: reduce partials -> bf16 hi/lo KV + fp32 Ksum.
// ---------------------------------------------------------------------------
__global__ void __launch_bounds__(256) reduce_kernel() {
    const int nh = blockIdx.x;
    const int i4 = blockIdx.y * 256 + threadIdx.x;   // float4 index 0..1023
    float4 s = make_float4(0.f, 0.f, 0.f, 0.f);
    const float4* base = (const float4*)g_partKV;
#pragma unroll
    for (int p = 0; p < SPLIT; p++) {
        const float4 v = base[((size_t)p * NH + nh) * 1024 + i4];
        s.x += v.x; s.y += v.y; s.z += v.z; s.w += v.w;
    }
    __nv_bfloat16 hx = __float2bfloat16(s.x), hy = __float2bfloat16(s.y);
    __nv_bfloat16 hz = __float2bfloat16(s.z), hw = __float2bfloat16(s.w);
    __nv_bfloat16 lx = __float2bfloat16(s.x - __bfloat162float(hx));
    __nv_bfloat16 ly = __float2bfloat16(s.y - __bfloat162float(hy));
    __nv_bfloat16 lz = __float2bfloat16(s.z - __bfloat162float(hz));
    __nv_bfloat16 lw = __float2bfloat16(s.w - __bfloat162float(hw));
    ((uint2*)(g_KVhi + (size_t)nh * 4096))[i4] =
        make_uint2(pack_bf16x2(hx, hy), pack_bf16x2(hz, hw));
    ((uint2*)(g_KVlo + (size_t)nh * 4096))[i4] =
        make_uint2(pack_bf16x2(lx, ly), pack_bf16x2(lz, lw));

    if (blockIdx.y == 0 && threadIdx.x < 64) {
        float z = 0.0f;
#pragma unroll
        for (int p = 0; p < SPLIT; p++)
            z += g_partKs[((size_t)p * NH + nh) * D_K + threadIdx.x];
        g_Ksum[nh * D_K + threadIdx.x] = z;
    }
}

// ---------------------------------------------------------------------------
// Kernel 3 (HMMA): out[l][v] = (Qf[l].KV[:,v]) * Z[l]. Hoisted fragments:
// per k-step 2 A ldmatrix, per n-pair 2 B ldmatrix, 6 mma from registers
// (40 ldmatrix total, was 60). Data layouts and mappings unchanged (proven).
// ---------------------------------------------------------------------------
__global__ void __launch_bounds__(128) out_kernel(const float* __restrict__ Qg,
                                                  float* __restrict__ Og) {
    __shared__ __align__(16) __nv_bfloat16 sQhi[64][QS];
    __shared__ __align__(16) __nv_bfloat16 sQlo[64][QS];
    __shared__ __align__(16) __nv_bfloat16 sBhi[64][QS];
    __shared__ __align__(16) __nv_bfloat16 sBlo[64][QS];
    __shared__ __align__(16) float sKs[64];
    __shared__ __align__(16) float sZ[64];

    const int nh = blockIdx.y;
    const int l0 = blockIdx.x * 64;
    const int n  = nh >> 3;
    const int h  = nh & 7;
    const int t  = threadIdx.x;

    if (t < 64) sKs[t] = g_Ksum[nh * D_K + t];

    {
        const uint4* bh = (const uint4*)(g_KVhi + (size_t)nh * 4096);
        const uint4* bl = (const uint4*)(g_KVlo + (size_t)nh * 4096);
#pragma unroll
        for (int i = 0; i < 4; i++) {
            const int idx = i * 128 + t;
            const int row = idx >> 3, cg = idx & 7;
            *(uint4*)&sBhi[row][8 * cg] = bh[idx];
            *(uint4*)&sBlo[row][8 * cg] = bl[idx];
        }
    }
    __syncthreads();

    {
        const int qr = t >> 4;
        const int qc = (t & 15) * 4;
        const float* Qb = Qg + ((size_t)n * L_LEN + l0) * ROWSTR + h * D_K;
        float zp[8];
#pragma unroll
        for (int p = 0; p < 8; p++) zp[p] = 0.0f;
#pragma unroll
        for (int p = 0; p < 8; p++) {
            const int l = p * 8 + qr;
            float4 q = *(const float4*)(Qb + (size_t)l * ROWSTR + qc);
            const float f0 = elu1(q.x), f1 = elu1(q.y), f2 = elu1(q.z), f3 = elu1(q.w);
            zp[p] = f0 * sKs[qc] + f1 * sKs[qc + 1] + f2 * sKs[qc + 2] + f3 * sKs[qc + 3];
            const __nv_bfloat16 h0 = __float2bfloat16(f0), h1 = __float2bfloat16(f1);
            const __nv_bfloat16 h2 = __float2bfloat16(f2), h3 = __float2bfloat16(f3);
            *(uint2*)&sQhi[l][qc] = make_uint2(pack_bf16x2(h0, h1), pack_bf16x2(h2, h3));
            *(uint2*)&sQlo[l][qc] = make_uint2(
                pack_bf16x2(__float2bfloat16(f0 - __bfloat162float(h0)),
                            __float2bfloat16(f1 - __bfloat162float(h1))),
                pack_bf16x2(__float2bfloat16(f2 - __bfloat162float(h2)),
                            __float2bfloat16(f3 - __bfloat162float(h3))));
        }
#pragma unroll
        for (int p = 0; p < 8; p++) {
#pragma unroll
            for (int o = 8; o > 0; o >>= 1)
                zp[p] += __shfl_xor_sync(0xFFFFFFFFu, zp[p], o, 16);
        }
        const int c = t & 15;
        if (c < 8) sZ[c * 8 + qr] = 1.0f / (zp[c] + 1e-6f);
    }
    __syncthreads();

    const int w    = t >> 5;
    const int lane = t & 31;
    const int L    = 16 * w;

    const int arow = L + (lane & 7) + ((lane >> 3) & 1) * 8;
    const int acol = ((lane >> 4) & 1) * 8;
    const int brow = (lane & 7) + ((lane >> 3) & 1) * 8;
    const int bcol = ((lane >> 4) & 1) * 8;

    float acc[8][4];
#pragma unroll
    for (int nt = 0; nt < 8; nt++)
#pragma unroll
        for (int i = 0; i < 4; i++) acc[nt][i] = 0.0f;

    const uint32_t aQhi = smem_u32(&sQhi[arow][acol]);
    const uint32_t aQlo = smem_u32(&sQlo[arow][acol]);
    const uint32_t aBhi = smem_u32(&sBhi[brow][bcol]);
    const uint32_t aBlo = smem_u32(&sBlo[brow][bcol]);

#pragma unroll
    for (int k = 0; k < 4; k++) {
        const uint4 ahi = ldm_x4(aQhi + (uint32_t)(16 * k) * 2);
        const uint4 alo = ldm_x4(aQlo + (uint32_t)(16 * k) * 2);
#pragma unroll
        for (int np = 0; np < 4; np++) {
            const uint32_t boff = ((uint32_t)(16 * k) * QS + (uint32_t)(16 * np)) * 2;
            const uint4 bhi = ldm_x4t(aBhi + boff);
            const uint4 blo = ldm_x4t(aBlo + boff);
            mma_bf16(acc[2 * np],     ahi, bhi.x, bhi.y);
            mma_bf16(acc[2 * np],     ahi, blo.x, blo.y);
            mma_bf16(acc[2 * np],     alo, bhi.x, bhi.y);
            mma_bf16(acc[2 * np + 1], ahi, bhi.z, bhi.w);
            mma_bf16(acc[2 * np + 1], ahi, blo.z, blo.w);
            mma_bf16(acc[2 * np + 1], alo, bhi.z, bhi.w);
        }
    }

    {
        const int r0 = L + (lane >> 2);
        const int r1 = r0 + 8;
        const float z0 = sZ[r0], z1 = sZ[r1];
        float* o0 = Og + ((size_t)(n * L_LEN + l0 + r0)) * ROWSTR + h * D_K;
        float* o1 = Og + ((size_t)(n * L_LEN + l0 + r1)) * ROWSTR + h * D_K;
        const int cb = 2 * (lane & 3);
#pragma unroll
        for (int nt = 0; nt < 8; nt++) {
            *(float2*)(o0 + 8 * nt + cb) = make_float2(acc[nt][0] * z0, acc[nt][1] * z0);
            *(float2*)(o1 + 8 * nt + cb) = make_float2(acc[nt][2] * z1, acc[nt][3] * z1);
        }
    }
}

// ---------------------------------------------------------------------------
extern "C" void kernel_launch(void* const* d_in, const int* in_sizes, int n_in,
                              void* d_out, int out_size) {
    (void)in_sizes; (void)n_in; (void)out_size;
    const float* Q = (const float*)d_in[0];
    const float* K = (const float*)d_in[1];
    const float* V = (const float*)d_in[2];
    float* O = (float*)d_out;

    kv_kernel<<<dim3(SPLIT, NH), 128>>>(K, V);
    reduce_kernel<<<dim3(NH, 4), 256>>>();
    out_kernel<<<dim3(L_LEN / 64, NH), 128>>>(Q, O);
}

// round 14
// speedup vs baseline: 2.5351x; 1.0050x over previous
#include <cuda_runtime.h>
#include <cuda_bf16.h>
#include <cstdint>

typedef unsigned long long ull;

#define N_B    4
#define H_N    8
#define D_K    64
#define S_LEN  4096
#define L_LEN  4096
#define NH     32
#define ROWSTR 512               // floats between consecutive s/l rows
#define SPLIT  16
#define CHUNK  256               // S_LEN / SPLIT
#define KSTAGE 32                // s-rows per double-buffered stage
#define NSTG   (CHUNK / KSTAGE)  // 8
#define QS     72                // smem row stride in bf16 halves (144B = 9x16B)

// Persistent scratch (device globals; no runtime allocation).
__device__ float g_partKV[SPLIT * NH * D_K * D_K];   // [split][nh][d][v]
__device__ float g_partKs[SPLIT * NH * D_K];         // [split][nh][d]
__device__ __nv_bfloat16 g_KVhi[NH * D_K * D_K];     // [nh][d][v] bf16 high part
__device__ __nv_bfloat16 g_KVlo[NH * D_K * D_K];     // [nh][d][v] bf16 low part
__device__ float g_Ksum[NH * D_K];                   // [nh][d]

__device__ __forceinline__ float elu1(float x) {
    return x > 0.0f ? x + 1.0f : __expf(x);
}
__device__ __forceinline__ uint32_t smem_u32(const void* p) {
    uint32_t a;
    asm("{ .reg .u64 tmp; cvta.to.shared.u64 tmp, %1; cvt.u32.u64 %0, tmp; }"
        : "=r"(a) : "l"(p));
    return a;
}
__device__ __forceinline__ uint32_t pack_bf16x2(__nv_bfloat16 a, __nv_bfloat16 b) {
    __nv_bfloat162 t = __halves2bfloat162(a, b);
    return *reinterpret_cast<uint32_t*>(&t);
}
__device__ __forceinline__ uint4 ldm_x4(uint32_t addr) {
    uint4 r;
    asm volatile("ldmatrix.sync.aligned.m8n8.x4.shared.b16 {%0,%1,%2,%3}, [%4];"
                 : "=r"(r.x), "=r"(r.y), "=r"(r.z), "=r"(r.w) : "r"(addr));
    return r;
}
__device__ __forceinline__ uint4 ldm_x4t(uint32_t addr) {
    uint4 r;
    asm volatile("ldmatrix.sync.aligned.m8n8.x4.trans.shared.b16 {%0,%1,%2,%3}, [%4];"
                 : "=r"(r.x), "=r"(r.y), "=r"(r.z), "=r"(r.w) : "r"(addr));
    return r;
}
__device__ __forceinline__ void mma_bf16(float* c, uint4 a, uint32_t b0, uint32_t b1) {
    asm volatile(
        "mma.sync.aligned.m16n8k16.row.col.f32.bf16.bf16.f32 "
        "{%0,%1,%2,%3}, {%4,%5,%6,%7}, {%8,%9}, {%0,%1,%2,%3};"
        : "+f"(c[0]), "+f"(c[1]), "+f"(c[2]), "+f"(c[3])
        : "r"(a.x), "r"(a.y), "r"(a.z), "r"(a.w), "r"(b0), "r"(b1));
}

// ---------------------------------------------------------------------------
// Kernel 1 (HMMA): partial KV[d][v] += K^T V over an S-chunk, + partial Ksum.
// Loader stores are STS.128 (uint4): with 144B row stride (9 x 16B), the
// quarter-warp phase hits 16B-groups (r + 2c + i) mod 8, all distinct ->
// conflict-free (the old STS.64 pattern was 4-way conflicted on every store).
// ---------------------------------------------------------------------------
__global__ void __launch_bounds__(128) kv_kernel(const float* __restrict__ Kg,
                                                 const float* __restrict__ Vg) {
    __shared__ __align__(16) __nv_bfloat16 sKhi[2][KSTAGE][QS];
    __shared__ __align__(16) __nv_bfloat16 sKlo[2][KSTAGE][QS];
    __shared__ __align__(16) __nv_bfloat16 sVhi[2][KSTAGE][QS];
    __shared__ __align__(16) __nv_bfloat16 sVlo[2][KSTAGE][QS];
    __shared__ __align__(16) float sRed[KSTAGE][64];

    const int split = blockIdx.x;
    const int nh    = blockIdx.y;
    const int n     = nh >> 3;
    const int h     = nh & 7;

    const size_t rowbase = ((size_t)n * S_LEN + (size_t)split * CHUNK) * ROWSTR + h * D_K;
    const float* Kb = Kg + rowbase;
    const float* Vb = Vg + rowbase;

    const int t  = threadIdx.x;
    const int lr = t >> 2;               // loader row 0..31
    const int c0 = (t & 3) * 16;         // loader col base (16 cols per thread)

    const float* kp = Kb + (size_t)lr * ROWSTR + c0;
    const float* vp = Vb + (size_t)lr * ROWSTR + c0;

    float ks[16];
#pragma unroll
    for (int i = 0; i < 16; i++) ks[i] = 0.0f;

    float4 pk[4], pv[4];
#pragma unroll
    for (int i = 0; i < 4; i++) {
        pk[i] = *(const float4*)(kp + 4 * i);
        pv[i] = *(const float4*)(vp + 4 * i);
    }

    auto store_stage = [&](int b) {
        // Convert 16 K values (elu + hi/lo split) and 16 V values (hi/lo).
        uint32_t khi[8], klo[8], vhi[8], vlo[8];
#pragma unroll
        for (int i = 0; i < 4; i++) {
            const float f0 = elu1(pk[i].x), f1 = elu1(pk[i].y);
            const float f2 = elu1(pk[i].z), f3 = elu1(pk[i].w);
            ks[4 * i] += f0; ks[4 * i + 1] += f1;
            ks[4 * i + 2] += f2; ks[4 * i + 3] += f3;
            const __nv_bfloat16 h0 = __float2bfloat16(f0), h1 = __float2bfloat16(f1);
            const __nv_bfloat16 h2 = __float2bfloat16(f2), h3 = __float2bfloat16(f3);
            khi[2 * i]     = pack_bf16x2(h0, h1);
            khi[2 * i + 1] = pack_bf16x2(h2, h3);
            klo[2 * i]     = pack_bf16x2(__float2bfloat16(f0 - __bfloat162float(h0)),
                                         __float2bfloat16(f1 - __bfloat162float(h1)));
            klo[2 * i + 1] = pack_bf16x2(__float2bfloat16(f2 - __bfloat162float(h2)),
                                         __float2bfloat16(f3 - __bfloat162float(h3)));
            const float g0 = pv[i].x, g1 = pv[i].y, g2 = pv[i].z, g3 = pv[i].w;
            const __nv_bfloat16 e0 = __float2bfloat16(g0), e1 = __float2bfloat16(g1);
            const __nv_bfloat16 e2 = __float2bfloat16(g2), e3 = __float2bfloat16(g3);
            vhi[2 * i]     = pack_bf16x2(e0, e1);
            vhi[2 * i + 1] = pack_bf16x2(e2, e3);
            vlo[2 * i]     = pack_bf16x2(__float2bfloat16(g0 - __bfloat162float(e0)),
                                         __float2bfloat16(g1 - __bfloat162float(e1)));
            vlo[2 * i + 1] = pack_bf16x2(__float2bfloat16(g2 - __bfloat162float(e2)),
                                         __float2bfloat16(g3 - __bfloat162float(e3)));
        }
        // Two conflict-free STS.128 per array.
#pragma unroll
        for (int ii = 0; ii < 2; ii++) {
            *(uint4*)&sKhi[b][lr][c0 + 8 * ii] =
                make_uint4(khi[4 * ii], khi[4 * ii + 1], khi[4 * ii + 2], khi[4 * ii + 3]);
            *(uint4*)&sKlo[b][lr][c0 + 8 * ii] =
                make_uint4(klo[4 * ii], klo[4 * ii + 1], klo[4 * ii + 2], klo[4 * ii + 3]);
            *(uint4*)&sVhi[b][lr][c0 + 8 * ii] =
                make_uint4(vhi[4 * ii], vhi[4 * ii + 1], vhi[4 * ii + 2], vhi[4 * ii + 3]);
            *(uint4*)&sVlo[b][lr][c0 + 8 * ii] =
                make_uint4(vlo[4 * ii], vlo[4 * ii + 1], vlo[4 * ii + 2], vlo[4 * ii + 3]);
        }
    };

    store_stage(0);
    __syncthreads();

    // MMA lane addressing (verified in R12).
    const int w    = t >> 5;
    const int lane = t & 31;
    const int arow = (lane & 7) + ((lane >> 4) & 1) * 8;
    const int acol = 16 * w + ((lane >> 3) & 1) * 8;
    const int brow = (lane & 7) + ((lane >> 3) & 1) * 8;
    const int bcol = ((lane >> 4) & 1) * 8;

    const uint32_t aKhi = smem_u32(&sKhi[0][arow][acol]);
    const uint32_t aKlo = smem_u32(&sKlo[0][arow][acol]);
    const uint32_t aVhi = smem_u32(&sVhi[0][brow][bcol]);
    const uint32_t aVlo = smem_u32(&sVlo[0][brow][bcol]);
    const uint32_t bufB = KSTAGE * QS * 2;   // bytes per buffer
    const uint32_t ktB  = 16 * QS * 2;       // bytes per 16-row k-step

    float acc[8][4];
#pragma unroll
    for (int nt = 0; nt < 8; nt++)
#pragma unroll
        for (int i = 0; i < 4; i++) acc[nt][i] = 0.0f;

    for (int st = 0; st < NSTG; st++) {
        const int cur = st & 1;
        if (st < NSTG - 1) {
            const float* kp2 = kp + (size_t)(st + 1) * KSTAGE * ROWSTR;
            const float* vp2 = vp + (size_t)(st + 1) * KSTAGE * ROWSTR;
#pragma unroll
            for (int i = 0; i < 4; i++) {
                pk[i] = *(const float4*)(kp2 + 4 * i);
                pv[i] = *(const float4*)(vp2 + 4 * i);
            }
        }

        const uint32_t bo = cur * bufB;
#pragma unroll
        for (int k = 0; k < 2; k++) {
            const uint4 ahi = ldm_x4t(aKhi + bo + k * ktB);
            const uint4 alo = ldm_x4t(aKlo + bo + k * ktB);
#pragma unroll
            for (int np = 0; np < 4; np++) {
                const uint32_t boff = bo + k * ktB + (uint32_t)(16 * np) * 2;
                const uint4 bhi = ldm_x4t(aVhi + boff);
                const uint4 blo = ldm_x4t(aVlo + boff);
                mma_bf16(acc[2 * np],     ahi, bhi.x, bhi.y);
                mma_bf16(acc[2 * np],     ahi, blo.x, blo.y);
                mma_bf16(acc[2 * np],     alo, bhi.x, bhi.y);
                mma_bf16(acc[2 * np + 1], ahi, bhi.z, bhi.w);
                mma_bf16(acc[2 * np + 1], ahi, blo.z, blo.w);
                mma_bf16(acc[2 * np + 1], alo, bhi.z, bhi.w);
            }
        }

        if (st < NSTG - 1) store_stage(cur ^ 1);
        __syncthreads();
    }

    // Ksum: each thread wrote partial sums for its 16 cols over all its rows.
#pragma unroll
    for (int i = 0; i < 16; i++) sRed[lr][c0 + i] = ks[i];
    __syncthreads();
    if (t < 64) {
        float s = 0.0f;
#pragma unroll
        for (int r = 0; r < KSTAGE; r++) s += sRed[r][t];
        g_partKs[((size_t)split * NH + nh) * D_K + t] = s;
    }

    // Store partial KV fragments.
    {
        float* dst = g_partKV + ((size_t)split * NH + nh) * (D_K * D_K);
        const int r0 = 16 * w + (lane >> 2);
        const int r1 = r0 + 8;
        const int cb = 2 * (lane & 3);
#pragma unroll
        for (int nt = 0; nt < 8; nt++) {
            *(float2*)(dst + r0 * 64 + 8 * nt + cb) = make_float2(acc[nt][0], acc[nt][1]);
            *(float2*)(dst + r1 * 64 + 8 * nt + cb) = make_float2(acc[nt][2], acc[nt][3]);
        }
    }
}

// ---------------------------------------------------------------------------
// Kernel 2: reduce partials -> bf16 hi/lo KV + fp32 Ksum.
// ---------------------------------------------------------------------------
__global__ void __launch_bounds__(256) reduce_kernel() {
    const int nh = blockIdx.x;
    const int i4 = blockIdx.y * 256 + threadIdx.x;   // float4 index 0..1023
    float4 s = make_float4(0.f, 0.f, 0.f, 0.f);
    const float4* base = (const float4*)g_partKV;
#pragma unroll
    for (int p = 0; p < SPLIT; p++) {
        const float4 v = base[((size_t)p * NH + nh) * 1024 + i4];
        s.x += v.x; s.y += v.y; s.z += v.z; s.w += v.w;
    }
    __nv_bfloat16 hx = __float2bfloat16(s.x), hy = __float2bfloat16(s.y);
    __nv_bfloat16 hz = __float2bfloat16(s.z), hw = __float2bfloat16(s.w);
    __nv_bfloat16 lx = __float2bfloat16(s.x - __bfloat162float(hx));
    __nv_bfloat16 ly = __float2bfloat16(s.y - __bfloat162float(hy));
    __nv_bfloat16 lz = __float2bfloat16(s.z - __bfloat162float(hz));
    __nv_bfloat16 lw = __float2bfloat16(s.w - __bfloat162float(hw));
    ((uint2*)(g_KVhi + (size_t)nh * 4096))[i4] =
        make_uint2(pack_bf16x2(hx, hy), pack_bf16x2(hz, hw));
    ((uint2*)(g_KVlo + (size_t)nh * 4096))[i4] =
        make_uint2(pack_bf16x2(lx, ly), pack_bf16x2(lz, lw));

    if (blockIdx.y == 0 && threadIdx.x < 64) {
        float z = 0.0f;
#pragma unroll
        for (int p = 0; p < SPLIT; p++)
            z += g_partKs[((size_t)p * NH + nh) * D_K + threadIdx.x];
        g_Ksum[nh * D_K + threadIdx.x] = z;
    }
}

// ---------------------------------------------------------------------------
// Kernel 3 (HMMA, proven R13): out[l][v] = (Qf[l].KV[:,v]) * Z[l].
// Hoisted fragments: 2 A + 2 B ldmatrix feed 6 mma from registers.
// ---------------------------------------------------------------------------
__global__ void __launch_bounds__(128) out_kernel(const float* __restrict__ Qg,
                                                  float* __restrict__ Og) {
    __shared__ __align__(16) __nv_bfloat16 sQhi[64][QS];
    __shared__ __align__(16) __nv_bfloat16 sQlo[64][QS];
    __shared__ __align__(16) __nv_bfloat16 sBhi[64][QS];
    __shared__ __align__(16) __nv_bfloat16 sBlo[64][QS];
    __shared__ __align__(16) float sKs[64];
    __shared__ __align__(16) float sZ[64];

    const int nh = blockIdx.y;
    const int l0 = blockIdx.x * 64;
    const int n  = nh >> 3;
    const int h  = nh & 7;
    const int t  = threadIdx.x;

    if (t < 64) sKs[t] = g_Ksum[nh * D_K + t];

    {
        const uint4* bh = (const uint4*)(g_KVhi + (size_t)nh * 4096);
        const uint4* bl = (const uint4*)(g_KVlo + (size_t)nh * 4096);
#pragma unroll
        for (int i = 0; i < 4; i++) {
            const int idx = i * 128 + t;
            const int row = idx >> 3, cg = idx & 7;
            *(uint4*)&sBhi[row][8 * cg] = bh[idx];
            *(uint4*)&sBlo[row][8 * cg] = bl[idx];
        }
    }
    __syncthreads();

    {
        const int qr = t >> 4;
        const int qc = (t & 15) * 4;
        const float* Qb = Qg + ((size_t)n * L_LEN + l0) * ROWSTR + h * D_K;
        float zp[8];
#pragma unroll
        for (int p = 0; p < 8; p++) zp[p] = 0.0f;
#pragma unroll
        for (int p = 0; p < 8; p++) {
            const int l = p * 8 + qr;
            float4 q = *(const float4*)(Qb + (size_t)l * ROWSTR + qc);
            const float f0 = elu1(q.x), f1 = elu1(q.y), f2 = elu1(q.z), f3 = elu1(q.w);
            zp[p] = f0 * sKs[qc] + f1 * sKs[qc + 1] + f2 * sKs[qc + 2] + f3 * sKs[qc + 3];
            const __nv_bfloat16 h0 = __float2bfloat16(f0), h1 = __float2bfloat16(f1);
            const __nv_bfloat16 h2 = __float2bfloat16(f2), h3 = __float2bfloat16(f3);
            *(uint2*)&sQhi[l][qc] = make_uint2(pack_bf16x2(h0, h1), pack_bf16x2(h2, h3));
            *(uint2*)&sQlo[l][qc] = make_uint2(
                pack_bf16x2(__float2bfloat16(f0 - __bfloat162float(h0)),
                            __float2bfloat16(f1 - __bfloat162float(h1))),
                pack_bf16x2(__float2bfloat16(f2 - __bfloat162float(h2)),
                            __float2bfloat16(f3 - __bfloat162float(h3))));
        }
#pragma unroll
        for (int p = 0; p < 8; p++) {
#pragma unroll
            for (int o = 8; o > 0; o >>= 1)
                zp[p] += __shfl_xor_sync(0xFFFFFFFFu, zp[p], o, 16);
        }
        const int c = t & 15;
        if (c < 8) sZ[c * 8 + qr] = 1.0f / (zp[c] + 1e-6f);
    }
    __syncthreads();

    const int w    = t >> 5;
    const int lane = t & 31;
    const int L    = 16 * w;

    const int arow = L + (lane & 7) + ((lane >> 3) & 1) * 8;
    const int acol = ((lane >> 4) & 1) * 8;
    const int brow = (lane & 7) + ((lane >> 3) & 1) * 8;
    const int bcol = ((lane >> 4) & 1) * 8;

    float acc[8][4];
#pragma unroll
    for (int nt = 0; nt < 8; nt++)
#pragma unroll
        for (int i = 0; i < 4; i++) acc[nt][i] = 0.0f;

    const uint32_t aQhi = smem_u32(&sQhi[arow][acol]);
    const uint32_t aQlo = smem_u32(&sQlo[arow][acol]);
    const uint32_t aBhi = smem_u32(&sBhi[brow][bcol]);
    const uint32_t aBlo = smem_u32(&sBlo[brow][bcol]);

#pragma unroll
    for (int k = 0; k < 4; k++) {
        const uint4 ahi = ldm_x4(aQhi + (uint32_t)(16 * k) * 2);
        const uint4 alo = ldm_x4(aQlo + (uint32_t)(16 * k) * 2);
#pragma unroll
        for (int np = 0; np < 4; np++) {
            const uint32_t boff = ((uint32_t)(16 * k) * QS + (uint32_t)(16 * np)) * 2;
            const uint4 bhi = ldm_x4t(aBhi + boff);
            const uint4 blo = ldm_x4t(aBlo + boff);
            mma_bf16(acc[2 * np],     ahi, bhi.x, bhi.y);
            mma_bf16(acc[2 * np],     ahi, blo.x, blo.y);
            mma_bf16(acc[2 * np],     alo, bhi.x, bhi.y);
            mma_bf16(acc[2 * np + 1], ahi, bhi.z, bhi.w);
            mma_bf16(acc[2 * np + 1], ahi, blo.z, blo.w);
            mma_bf16(acc[2 * np + 1], alo, bhi.z, bhi.w);
        }
    }

    {
        const int r0 = L + (lane >> 2);
        const int r1 = r0 + 8;
        const float z0 = sZ[r0], z1 = sZ[r1];
        float* o0 = Og + ((size_t)(n * L_LEN + l0 + r0)) * ROWSTR + h * D_K;
        float* o1 = Og + ((size_t)(n * L_LEN + l0 + r1)) * ROWSTR + h * D_K;
        const int cb = 2 * (lane & 3);
#pragma unroll
        for (int nt = 0; nt < 8; nt++) {
            *(float2*)(o0 + 8 * nt + cb) = make_float2(acc[nt][0] * z0, acc[nt][1] * z0);
            *(float2*)(o1 + 8 * nt + cb) = make_float2(acc[nt][2] * z1, acc[nt][3] * z1);
        }
    }
}

// ---------------------------------------------------------------------------
extern "C" void kernel_launch(void* const* d_in, const int* in_sizes, int n_in,
                              void* d_out, int out_size) {
    (void)in_sizes; (void)n_in; (void)out_size;
    const float* Q = (const float*)d_in[0];
    const float* K = (const float*)d_in[1];
    const float* V = (const float*)d_in[2];
    float* O = (float*)d_out;

    kv_kernel<<<dim3(SPLIT, NH), 128>>>(K, V);
    reduce_kernel<<<dim3(NH, 4), 256>>>();
    out_kernel<<<dim3(L_LEN / 64, NH), 128>>>(Q, O);
}